// round 5
// baseline (speedup 1.0000x reference)
#include <cuda_runtime.h>

#define B 8
#define T 1024
#define D 512
#define H 8
#define DK 64
#define BT (B*T)   // 8192

__device__ float g_q[BT * D];
__device__ float g_k[BT * D];
__device__ float g_v[BT * D];
__device__ float g_p[BT * D];
__device__ float g_cs[(size_t)B * H * T * T];
__device__ float g_ps[(size_t)B * H * T * T];
__device__ float g_ctx[BT * D];

__device__ __forceinline__ float f2tf32(float f) {
    unsigned u;
    asm("cvt.rna.tf32.f32 %0, %1;" : "=r"(u) : "f"(f));
    return __uint_as_float(u);
}

// mma.sync m16n8k8 tf32 row.col
__device__ __forceinline__ void mma_tf32(float* c, const float* a, const float* b) {
    asm volatile(
        "mma.sync.aligned.m16n8k8.row.col.f32.tf32.tf32.f32 "
        "{%0,%1,%2,%3}, {%4,%5,%6,%7}, {%8,%9}, {%0,%1,%2,%3};"
        : "+f"(c[0]), "+f"(c[1]), "+f"(c[2]), "+f"(c[3])
        : "r"(__float_as_uint(a[0])), "r"(__float_as_uint(a[1])),
          "r"(__float_as_uint(a[2])), "r"(__float_as_uint(a[3])),
          "r"(__float_as_uint(b[0])), "r"(__float_as_uint(b[1])));
}

__device__ __forceinline__ void cp16(float* dst, const float* src) {
    unsigned d = (unsigned)__cvta_generic_to_shared(dst);
    asm volatile("cp.async.ca.shared.global [%0], [%1], 16;" :: "r"(d), "l"(src));
}
__device__ __forceinline__ void cp_commit() { asm volatile("cp.async.commit_group;"); }
__device__ __forceinline__ void cp_wait0()  { asm volatile("cp.async.wait_group 0;"); }

// ---------------------------------------------------------------------------
// GEMM: C[M,N] = A[M,K] @ W[K,N] (+bias). Block 128x128, 256 thr (8 warps 2x4),
// warp 64x32, K-step 16, register-staged double buffer, rounded tf32.
// ---------------------------------------------------------------------------
__global__ __launch_bounds__(256) void sgemm_bias_tc(
    const float* __restrict__ A, const float* __restrict__ W,
    const float* __restrict__ bias, float* __restrict__ C,
    int M, int N, int K)
{
    __shared__ float As[2][128][20];
    __shared__ float Bs[2][16][136];
    int tid = threadIdx.x, warp = tid >> 5, lane = tid & 31;
    int gid = lane >> 2, tig = lane & 3;
    int wm = warp & 1, wn = warp >> 1;
    int bm = blockIdx.y * 128, bn = blockIdx.x * 128;
    int arow = tid >> 2, ac4 = (tid & 3) * 4;
    int brow = tid >> 5, bc4 = (tid & 31) * 4;

    const float* Ap0 = A + (size_t)(bm + arow) * K + ac4;
    const float* Ap1 = A + (size_t)(bm + arow + 64) * K + ac4;
    const float* Wp0 = W + (size_t)brow * N + bn + bc4;
    const float* Wp1 = W + (size_t)(brow + 8) * N + bn + bc4;

    float4 sa0 = *(const float4*)Ap0;
    float4 sa1 = *(const float4*)Ap1;
    float4 sb0 = *(const float4*)Wp0;
    float4 sb1 = *(const float4*)Wp1;

    float acc[4][4][4] = {};
    int nsteps = K / 16;
    for (int s = 0; s < nsteps; s++) {
        int buf = s & 1;
        As[buf][arow][ac4+0] = f2tf32(sa0.x); As[buf][arow][ac4+1] = f2tf32(sa0.y);
        As[buf][arow][ac4+2] = f2tf32(sa0.z); As[buf][arow][ac4+3] = f2tf32(sa0.w);
        As[buf][arow+64][ac4+0] = f2tf32(sa1.x); As[buf][arow+64][ac4+1] = f2tf32(sa1.y);
        As[buf][arow+64][ac4+2] = f2tf32(sa1.z); As[buf][arow+64][ac4+3] = f2tf32(sa1.w);
        Bs[buf][brow][bc4+0] = f2tf32(sb0.x); Bs[buf][brow][bc4+1] = f2tf32(sb0.y);
        Bs[buf][brow][bc4+2] = f2tf32(sb0.z); Bs[buf][brow][bc4+3] = f2tf32(sb0.w);
        Bs[buf][brow+8][bc4+0] = f2tf32(sb1.x); Bs[buf][brow+8][bc4+1] = f2tf32(sb1.y);
        Bs[buf][brow+8][bc4+2] = f2tf32(sb1.z); Bs[buf][brow+8][bc4+3] = f2tf32(sb1.w);
        __syncthreads();

        if (s + 1 < nsteps) {
            int k0 = (s + 1) * 16;
            sa0 = *(const float4*)(Ap0 + k0);
            sa1 = *(const float4*)(Ap1 + k0);
            sb0 = *(const float4*)(Wp0 + (size_t)k0 * N);
            sb1 = *(const float4*)(Wp1 + (size_t)k0 * N);
        }

        #pragma unroll
        for (int k8 = 0; k8 < 2; k8++) {
            int kb = k8 * 8;
            float af[4][4], bf[4][2];
            #pragma unroll
            for (int mt = 0; mt < 4; mt++) {
                int r = wm * 64 + mt * 16 + gid;
                af[mt][0] = As[buf][r][kb + tig];
                af[mt][1] = As[buf][r + 8][kb + tig];
                af[mt][2] = As[buf][r][kb + tig + 4];
                af[mt][3] = As[buf][r + 8][kb + tig + 4];
            }
            #pragma unroll
            for (int nt = 0; nt < 4; nt++) {
                int c = wn * 32 + nt * 8 + gid;
                bf[nt][0] = Bs[buf][kb + tig][c];
                bf[nt][1] = Bs[buf][kb + tig + 4][c];
            }
            #pragma unroll
            for (int mt = 0; mt < 4; mt++)
                #pragma unroll
                for (int nt = 0; nt < 4; nt++)
                    mma_tf32(acc[mt][nt], af[mt], bf[nt]);
        }
        __syncthreads();
    }

    #pragma unroll
    for (int mt = 0; mt < 4; mt++) {
        int r0 = bm + wm * 64 + mt * 16 + gid;
        #pragma unroll
        for (int nt = 0; nt < 4; nt++) {
            int c0 = bn + wn * 32 + nt * 8 + 2 * tig;
            float b0 = bias ? bias[c0] : 0.f;
            float b1 = bias ? bias[c0 + 1] : 0.f;
            C[(size_t)r0 * N + c0]           = acc[mt][nt][0] + b0;
            C[(size_t)r0 * N + c0 + 1]       = acc[mt][nt][1] + b1;
            C[(size_t)(r0 + 8) * N + c0]     = acc[mt][nt][2] + b0;
            C[(size_t)(r0 + 8) * N + c0 + 1] = acc[mt][nt][3] + b1;
        }
    }
}

// ---------------------------------------------------------------------------
// Fused scores: 128x128 tiles of cs = scale*(q+u)·k and ps = scale*(q+v)·p.
// ---------------------------------------------------------------------------
#define QSTR 68
__device__ __forceinline__ void score_mma_store(
    const float* __restrict__ Q, const float* __restrict__ KP,
    float* __restrict__ out, size_t obase, int bi, int bj,
    int wm, int wn, int gid, int tig)
{
    float acc[4][4][4] = {};
    #pragma unroll
    for (int k8 = 0; k8 < 8; k8++) {
        int kb = k8 * 8;
        float af[4][4], bf[4][2];
        #pragma unroll
        for (int mt = 0; mt < 4; mt++) {
            int r = wm * 64 + mt * 16 + gid;
            af[mt][0] = Q[r * QSTR + kb + tig];
            af[mt][1] = Q[(r + 8) * QSTR + kb + tig];
            af[mt][2] = Q[r * QSTR + kb + tig + 4];
            af[mt][3] = Q[(r + 8) * QSTR + kb + tig + 4];
        }
        #pragma unroll
        for (int nt = 0; nt < 4; nt++) {
            int c = wn * 32 + nt * 8 + gid;
            bf[nt][0] = KP[c * QSTR + kb + tig];
            bf[nt][1] = KP[c * QSTR + kb + tig + 4];
        }
        #pragma unroll
        for (int mt = 0; mt < 4; mt++)
            #pragma unroll
            for (int nt = 0; nt < 4; nt++)
                mma_tf32(acc[mt][nt], af[mt], bf[nt]);
    }
    const float scale = 0.04419417382415922f;   // 1/sqrt(512)
    #pragma unroll
    for (int mt = 0; mt < 4; mt++) {
        int r0 = bi + wm * 64 + mt * 16 + gid;
        #pragma unroll
        for (int nt = 0; nt < 4; nt++) {
            int c0 = bj + wn * 32 + nt * 8 + 2 * tig;
            out[obase + (size_t)r0 * T + c0]           = acc[mt][nt][0] * scale;
            out[obase + (size_t)r0 * T + c0 + 1]       = acc[mt][nt][1] * scale;
            out[obase + (size_t)(r0 + 8) * T + c0]     = acc[mt][nt][2] * scale;
            out[obase + (size_t)(r0 + 8) * T + c0 + 1] = acc[mt][nt][3] * scale;
        }
    }
}

__global__ __launch_bounds__(256) void score_fused(
    const float* __restrict__ q, const float* __restrict__ k,
    const float* __restrict__ p, const float* __restrict__ ub,
    const float* __restrict__ vb, float* __restrict__ cs, float* __restrict__ ps)
{
    extern __shared__ float sm[];
    float* Qu = sm;
    float* Qv = sm + 128 * QSTR;
    float* KP = sm + 2 * 128 * QSTR;

    int bh = blockIdx.z, b = bh >> 3, h = bh & 7;
    int bi = blockIdx.y * 128, bj = blockIdx.x * 128;
    int tid = threadIdx.x, warp = tid >> 5, lane = tid & 31;
    int gid = lane >> 2, tig = lane & 3;
    int wm = warp & 1, wn = warp >> 1;
    size_t obase = (size_t)bh * T * T;

    #pragma unroll
    for (int l = 0; l < 8; l++) {
        int idx = tid + l * 256;
        int row = idx >> 4, c4 = (idx & 15) * 4;
        cp16(&KP[row * QSTR + c4], &k[(size_t)((b * T + bj + row) * H + h) * DK + c4]);
    }
    cp_commit();

    #pragma unroll
    for (int l = 0; l < 8; l++) {
        int idx = tid + l * 256;
        int row = idx >> 4, c4 = (idx & 15) * 4;
        float4 vq = *(const float4*)&q[(size_t)((b * T + bi + row) * H + h) * DK + c4];
        float4 uu = *(const float4*)&ub[h * DK + c4];
        float4 vv = *(const float4*)&vb[h * DK + c4];
        Qu[row * QSTR + c4 + 0] = f2tf32(vq.x + uu.x);
        Qu[row * QSTR + c4 + 1] = f2tf32(vq.y + uu.y);
        Qu[row * QSTR + c4 + 2] = f2tf32(vq.z + uu.z);
        Qu[row * QSTR + c4 + 3] = f2tf32(vq.w + uu.w);
        Qv[row * QSTR + c4 + 0] = f2tf32(vq.x + vv.x);
        Qv[row * QSTR + c4 + 1] = f2tf32(vq.y + vv.y);
        Qv[row * QSTR + c4 + 2] = f2tf32(vq.z + vv.z);
        Qv[row * QSTR + c4 + 3] = f2tf32(vq.w + vv.w);
    }
    cp_wait0();
    __syncthreads();

    score_mma_store(Qu, KP, cs, obase, bi, bj, wm, wn, gid, tig);
    __syncthreads();

    #pragma unroll
    for (int l = 0; l < 8; l++) {
        int idx = tid + l * 256;
        int row = idx >> 4, c4 = (idx & 15) * 4;
        cp16(&KP[row * QSTR + c4], &p[(size_t)((b * T + bj + row) * H + h) * DK + c4]);
    }
    cp_commit();
    cp_wait0();
    __syncthreads();

    score_mma_store(Qv, KP, ps, obase, bi, bj, wm, wn, gid, tig);
}

// ---------------------------------------------------------------------------
// Flash-style fused rel-shift + softmax + context.
// CTA = 128 query rows of one bh. Streams 128-wide j tiles:
//   shifted[r,j] = (j<=r)   ? ps[r,   T+j-r-1]
//                : (j==r+1) ? 0
//                :            ps[r+1, j-r-2]
// Online softmax with accumulator rescale; never materializes attn.
// ---------------------------------------------------------------------------
__global__ __launch_bounds__(256) void flash_softmax_ctx(
    const float* __restrict__ cs, const float* __restrict__ ps,
    const float* __restrict__ v, float* __restrict__ ctx)
{
    extern __shared__ float sm[];
    float* S   = sm;                        // [128][132] tf32 p-tile
    float* Vs  = sm + 128 * 132;            // [128][72]  v tile
    float* m_s = sm + 128 * 132 + 128 * 72; // [128]
    float* l_s = m_s + 128;
    float* f_s = l_s + 128;

    int bh = blockIdx.y, b = bh >> 3, h = bh & 7;
    int r0 = blockIdx.x * 128;
    int tid = threadIdx.x, warp = tid >> 5, lane = tid & 31;
    int gid = lane >> 2, tig = lane & 3;
    int wm = warp >> 1, wn = warp & 1;
    size_t base = (size_t)bh * T * T;

    if (tid < 128) { m_s[tid] = -1e30f; l_s[tid] = 0.f; }
    float acc[2][4][4] = {};
    __syncthreads();

    for (int j0 = 0; j0 < T; j0 += 128) {
        __syncthreads();   // protect S/f_s from previous tile's MMA readers

        // V tile (async, overlaps softmax phase)
        #pragma unroll
        for (int l = 0; l < 8; l++) {
            int idx = tid + l * 256;
            int row = idx >> 4, c4 = (idx & 15) * 4;
            cp16(&Vs[row * 72 + c4],
                 &v[(size_t)((b * T + j0 + row) * H + h) * DK + c4]);
        }
        cp_commit();

        // softmax phase: warp owns rows [warp*16, warp*16+16)
        for (int rr = 0; rr < 16; rr++) {
            int rl = warp * 16 + rr;
            int rg = r0 + rl;
            float sv[4];
            float mx = -1e30f;
            #pragma unroll
            for (int l = 0; l < 4; l++) {
                int jg = j0 + lane + l * 32;
                float psv;
                if (jg <= rg)
                    psv = ps[base + (size_t)rg * T + (T + jg - rg - 1)];
                else if (jg == rg + 1)
                    psv = 0.f;
                else
                    psv = ps[base + (size_t)(rg + 1) * T + (jg - rg - 2)];
                float s = cs[base + (size_t)rg * T + jg] + psv;
                sv[l] = s;
                mx = fmaxf(mx, s);
            }
            #pragma unroll
            for (int o = 16; o > 0; o >>= 1)
                mx = fmaxf(mx, __shfl_xor_sync(0xffffffffu, mx, o));
            float m_old = m_s[rl];
            float m_new = fmaxf(m_old, mx);
            float fct = __expf(m_old - m_new);
            float sum = 0.f;
            #pragma unroll
            for (int l = 0; l < 4; l++) {
                sv[l] = __expf(sv[l] - m_new);
                sum += sv[l];
            }
            #pragma unroll
            for (int o = 16; o > 0; o >>= 1)
                sum += __shfl_xor_sync(0xffffffffu, sum, o);
            if (lane == 0) {
                m_s[rl] = m_new;
                l_s[rl] = l_s[rl] * fct + sum;
                f_s[rl] = fct;
            }
            #pragma unroll
            for (int l = 0; l < 4; l++)
                S[rl * 132 + lane + l * 32] = f2tf32(sv[l]);
        }
        cp_wait0();
        __syncthreads();

        // rescale accumulator by per-row factor
        #pragma unroll
        for (int mt = 0; mt < 2; mt++) {
            int r1 = wm * 32 + mt * 16 + gid;
            float f1 = f_s[r1], f2 = f_s[r1 + 8];
            #pragma unroll
            for (int nt = 0; nt < 4; nt++) {
                acc[mt][nt][0] *= f1; acc[mt][nt][1] *= f1;
                acc[mt][nt][2] *= f2; acc[mt][nt][3] *= f2;
            }
        }

        // acc += S(128x128) @ V(128x64)
        #pragma unroll
        for (int k8 = 0; k8 < 16; k8++) {
            int kb = k8 * 8;
            float af[2][4], bf[4][2];
            #pragma unroll
            for (int mt = 0; mt < 2; mt++) {
                int r = wm * 32 + mt * 16 + gid;
                af[mt][0] = S[r * 132 + kb + tig];
                af[mt][1] = S[(r + 8) * 132 + kb + tig];
                af[mt][2] = S[r * 132 + kb + tig + 4];
                af[mt][3] = S[(r + 8) * 132 + kb + tig + 4];
            }
            #pragma unroll
            for (int nt = 0; nt < 4; nt++) {
                int c = wn * 32 + nt * 8 + gid;
                bf[nt][0] = Vs[(kb + tig) * 72 + c];
                bf[nt][1] = Vs[(kb + tig + 4) * 72 + c];
            }
            #pragma unroll
            for (int mt = 0; mt < 2; mt++)
                #pragma unroll
                for (int nt = 0; nt < 4; nt++)
                    mma_tf32(acc[mt][nt], af[mt], bf[nt]);
        }
    }

    #pragma unroll
    for (int mt = 0; mt < 2; mt++) {
        int r1 = wm * 32 + mt * 16 + gid;
        float rinv1 = 1.0f / l_s[r1];
        float rinv2 = 1.0f / l_s[r1 + 8];
        int rg1 = r0 + r1;
        #pragma unroll
        for (int nt = 0; nt < 4; nt++) {
            int c0 = wn * 32 + nt * 8 + 2 * tig;
            ctx[(size_t)((b * T + rg1) * H + h) * DK + c0]         = acc[mt][nt][0] * rinv1;
            ctx[(size_t)((b * T + rg1) * H + h) * DK + c0 + 1]     = acc[mt][nt][1] * rinv1;
            ctx[(size_t)((b * T + rg1 + 8) * H + h) * DK + c0]     = acc[mt][nt][2] * rinv2;
            ctx[(size_t)((b * T + rg1 + 8) * H + h) * DK + c0 + 1] = acc[mt][nt][3] * rinv2;
        }
    }
}

// ---------------------------------------------------------------------------
extern "C" void kernel_launch(void* const* d_in, const int* in_sizes, int n_in,
                              void* d_out, int out_size)
{
    const float* query = (const float*)d_in[0];
    const float* key   = (const float*)d_in[1];
    const float* value = (const float*)d_in[2];
    const float* pos   = (const float*)d_in[3];
    const float* Wq = (const float*)d_in[4];
    const float* bq = (const float*)d_in[5];
    const float* Wk = (const float*)d_in[6];
    const float* bk = (const float*)d_in[7];
    const float* Wv = (const float*)d_in[8];
    const float* bv = (const float*)d_in[9];
    const float* Wp = (const float*)d_in[10];
    const float* ub = (const float*)d_in[11];
    const float* vb = (const float*)d_in[12];
    const float* Wo = (const float*)d_in[13];
    const float* bo = (const float*)d_in[14];
    float* out = (float*)d_out;

    float *q, *k, *v, *p, *cs, *ps, *ctx;
    cudaGetSymbolAddress((void**)&q,   g_q);
    cudaGetSymbolAddress((void**)&k,   g_k);
    cudaGetSymbolAddress((void**)&v,   g_v);
    cudaGetSymbolAddress((void**)&p,   g_p);
    cudaGetSymbolAddress((void**)&cs,  g_cs);
    cudaGetSymbolAddress((void**)&ps,  g_ps);
    cudaGetSymbolAddress((void**)&ctx, g_ctx);

    const int SMEM_SCORE = 3 * 128 * QSTR * 4;                    // 104448 B
    const int SMEM_FLASH = (128 * 132 + 128 * 72 + 3 * 128) * 4;  // 105984 B
    cudaFuncSetAttribute(score_fused,
        cudaFuncAttributeMaxDynamicSharedMemorySize, SMEM_SCORE);
    cudaFuncSetAttribute(flash_softmax_ctx,
        cudaFuncAttributeMaxDynamicSharedMemorySize, SMEM_FLASH);

    dim3 gproj(D / 128, BT / 128);          // (4, 64)
    sgemm_bias_tc<<<gproj, 256>>>(query, Wq, bq, q, BT, D, D);
    sgemm_bias_tc<<<gproj, 256>>>(key,   Wk, bk, k, BT, D, D);
    sgemm_bias_tc<<<gproj, 256>>>(value, Wv, bv, v, BT, D, D);
    sgemm_bias_tc<<<gproj, 256>>>(pos,   Wp, nullptr, p, BT, D, D);

    dim3 gsc(T / 128, T / 128, B * H);      // (8, 8, 64)
    score_fused<<<gsc, 256, SMEM_SCORE>>>(q, k, p, ub, vb, cs, ps);

    dim3 gfl(T / 128, B * H);               // (8, 64)
    flash_softmax_ctx<<<gfl, 256, SMEM_FLASH>>>(cs, ps, v, ctx);

    sgemm_bias_tc<<<gproj, 256>>>(ctx, Wo, bo, out, BT, D, D);
}

// round 6
// speedup vs baseline: 1.3585x; 1.3585x over previous
#include <cuda_runtime.h>

#define B 8
#define T 1024
#define D 512
#define H 8
#define DK 64
#define BT (B*T)   // 8192

// Scratch (static device globals — no runtime allocation)
__device__ float g_q[BT * D];     // projection outputs (rounded tf32-in-fp32)
__device__ float g_k[BT * D];
__device__ float g_v[BT * D];
__device__ float g_p[BT * D];
__device__ float g_xq[BT * D];    // rounded copies of the 4 input activations
__device__ float g_xk[BT * D];
__device__ float g_xv[BT * D];
__device__ float g_xp[BT * D];
__device__ float g_w[5 * D * D];  // rounded weights Wq,Wk,Wv,Wp,Wo
__device__ float g_cs[(size_t)B * H * T * T];
__device__ float g_ps[(size_t)B * H * T * T];
__device__ float g_ctx[BT * D];

__device__ __forceinline__ float f2tf32(float f) {
    unsigned u;
    asm("cvt.rna.tf32.f32 %0, %1;" : "=r"(u) : "f"(f));
    return __uint_as_float(u);
}

// mma.sync m16n8k8 tf32 row.col
__device__ __forceinline__ void mma_tf32(float* c, const float* a, const float* b) {
    asm volatile(
        "mma.sync.aligned.m16n8k8.row.col.f32.tf32.tf32.f32 "
        "{%0,%1,%2,%3}, {%4,%5,%6,%7}, {%8,%9}, {%0,%1,%2,%3};"
        : "+f"(c[0]), "+f"(c[1]), "+f"(c[2]), "+f"(c[3])
        : "r"(__float_as_uint(a[0])), "r"(__float_as_uint(a[1])),
          "r"(__float_as_uint(a[2])), "r"(__float_as_uint(a[3])),
          "r"(__float_as_uint(b[0])), "r"(__float_as_uint(b[1])));
}

__device__ __forceinline__ void cp16(float* dst, const float* src) {
    unsigned d = (unsigned)__cvta_generic_to_shared(dst);
    asm volatile("cp.async.ca.shared.global [%0], [%1], 16;" :: "r"(d), "l"(src));
}
__device__ __forceinline__ void cp_commit() { asm volatile("cp.async.commit_group;"); }
__device__ __forceinline__ void cp_wait1()  { asm volatile("cp.async.wait_group 1;"); }
__device__ __forceinline__ void cp_wait0()  { asm volatile("cp.async.wait_group 0;"); }

// ---------------------------------------------------------------------------
// Pre-round pass: out[i] = round_to_tf32(in[i]).  n multiple of 1024.
// ---------------------------------------------------------------------------
__global__ __launch_bounds__(256) void round_pass(
    const float* __restrict__ in, float* __restrict__ out, int n4)
{
    int i = blockIdx.x * 256 + threadIdx.x;
    if (i < n4) {
        float4 v = ((const float4*)in)[i];
        v.x = f2tf32(v.x); v.y = f2tf32(v.y);
        v.z = f2tf32(v.z); v.w = f2tf32(v.w);
        ((float4*)out)[i] = v;
    }
}

// ---------------------------------------------------------------------------
// GEMM: C[M,N] = A[M,K] @ W[K,N] (+bias). Block 128x128, 128 thr (4 warps 2x2),
// warp tile 64x64, K-step 16, 3-stage cp.async pipeline. Inputs pre-rounded.
// ---------------------------------------------------------------------------
__global__ __launch_bounds__(128, 2) void sgemm_bias_tc(
    const float* __restrict__ A, const float* __restrict__ W,
    const float* __restrict__ bias, float* __restrict__ C,
    int M, int N, int K, int round_out)
{
    extern __shared__ float sm[];
    float (*As)[128][20] = reinterpret_cast<float(*)[128][20]>(sm);
    float (*Bs)[16][136] = reinterpret_cast<float(*)[16][136]>(sm + 3 * 128 * 20);

    int tid = threadIdx.x, warp = tid >> 5, lane = tid & 31;
    int gid = lane >> 2, tig = lane & 3;
    int wm = warp & 1, wn = warp >> 1;
    int bm = blockIdx.y * 128, bn = blockIdx.x * 128;
    int ar = tid;                         // A row (128 rows)
    int br = tid >> 3, bc = (tid & 7) * 16;   // B: 16 rows x 128 cols

    const float* Abase = A + (size_t)(bm + ar) * K;
    const float* Wbase = W + (size_t)br * N + bn + bc;
    int nsteps = K / 16;

    #pragma unroll
    for (int s = 0; s < 2; s++) {
        int k0 = s * 16;
        #pragma unroll
        for (int c = 0; c < 16; c += 4) {
            cp16(&As[s][ar][c],      Abase + k0 + c);
            cp16(&Bs[s][br][bc + c], Wbase + (size_t)k0 * N + c);
        }
        cp_commit();
    }

    float acc[4][8][4] = {};
    for (int s = 0; s < nsteps; s++) {
        cp_wait1();
        __syncthreads();
        int st = s % 3;
        if (s + 2 < nsteps) {
            int k0 = (s + 2) * 16, st2 = (s + 2) % 3;
            #pragma unroll
            for (int c = 0; c < 16; c += 4) {
                cp16(&As[st2][ar][c],      Abase + k0 + c);
                cp16(&Bs[st2][br][bc + c], Wbase + (size_t)k0 * N + c);
            }
        }
        cp_commit();

        #pragma unroll
        for (int k8 = 0; k8 < 2; k8++) {
            int kb = k8 * 8;
            float af[4][4], bf[8][2];
            #pragma unroll
            for (int mt = 0; mt < 4; mt++) {
                int r = wm * 64 + mt * 16 + gid;
                af[mt][0] = As[st][r][kb + tig];
                af[mt][1] = As[st][r + 8][kb + tig];
                af[mt][2] = As[st][r][kb + tig + 4];
                af[mt][3] = As[st][r + 8][kb + tig + 4];
            }
            #pragma unroll
            for (int nt = 0; nt < 8; nt++) {
                int c = wn * 64 + nt * 8 + gid;
                bf[nt][0] = Bs[st][kb + tig][c];
                bf[nt][1] = Bs[st][kb + tig + 4][c];
            }
            #pragma unroll
            for (int mt = 0; mt < 4; mt++)
                #pragma unroll
                for (int nt = 0; nt < 8; nt++)
                    mma_tf32(acc[mt][nt], af[mt], bf[nt]);
        }
    }

    #pragma unroll
    for (int mt = 0; mt < 4; mt++) {
        int r0 = bm + wm * 64 + mt * 16 + gid;
        #pragma unroll
        for (int nt = 0; nt < 8; nt++) {
            int c0 = bn + wn * 64 + nt * 8 + 2 * tig;
            float b0 = bias ? bias[c0] : 0.f;
            float b1 = bias ? bias[c0 + 1] : 0.f;
            float v0 = acc[mt][nt][0] + b0, v1 = acc[mt][nt][1] + b1;
            float v2 = acc[mt][nt][2] + b0, v3 = acc[mt][nt][3] + b1;
            if (round_out) {
                v0 = f2tf32(v0); v1 = f2tf32(v1);
                v2 = f2tf32(v2); v3 = f2tf32(v3);
            }
            C[(size_t)r0 * N + c0]           = v0;
            C[(size_t)r0 * N + c0 + 1]       = v1;
            C[(size_t)(r0 + 8) * N + c0]     = v2;
            C[(size_t)(r0 + 8) * N + c0 + 1] = v3;
        }
    }
}

// ---------------------------------------------------------------------------
// Fused scores: 128x128 tiles of cs = scale*(q+u)·k and ps = scale*(q+v)·p.
// ---------------------------------------------------------------------------
#define QSTR 68
__device__ __forceinline__ void score_mma_store(
    const float* __restrict__ Q, const float* __restrict__ KP,
    float* __restrict__ out, size_t obase, int bi, int bj,
    int wm, int wn, int gid, int tig)
{
    float acc[4][4][4] = {};
    #pragma unroll
    for (int k8 = 0; k8 < 8; k8++) {
        int kb = k8 * 8;
        float af[4][4], bf[4][2];
        #pragma unroll
        for (int mt = 0; mt < 4; mt++) {
            int r = wm * 64 + mt * 16 + gid;
            af[mt][0] = Q[r * QSTR + kb + tig];
            af[mt][1] = Q[(r + 8) * QSTR + kb + tig];
            af[mt][2] = Q[r * QSTR + kb + tig + 4];
            af[mt][3] = Q[(r + 8) * QSTR + kb + tig + 4];
        }
        #pragma unroll
        for (int nt = 0; nt < 4; nt++) {
            int c = wn * 32 + nt * 8 + gid;
            bf[nt][0] = KP[c * QSTR + kb + tig];
            bf[nt][1] = KP[c * QSTR + kb + tig + 4];
        }
        #pragma unroll
        for (int mt = 0; mt < 4; mt++)
            #pragma unroll
            for (int nt = 0; nt < 4; nt++)
                mma_tf32(acc[mt][nt], af[mt], bf[nt]);
    }
    const float scale = 0.04419417382415922f;   // 1/sqrt(512)
    #pragma unroll
    for (int mt = 0; mt < 4; mt++) {
        int r0 = bi + wm * 64 + mt * 16 + gid;
        #pragma unroll
        for (int nt = 0; nt < 4; nt++) {
            int c0 = bj + wn * 32 + nt * 8 + 2 * tig;
            out[obase + (size_t)r0 * T + c0]           = acc[mt][nt][0] * scale;
            out[obase + (size_t)r0 * T + c0 + 1]       = acc[mt][nt][1] * scale;
            out[obase + (size_t)(r0 + 8) * T + c0]     = acc[mt][nt][2] * scale;
            out[obase + (size_t)(r0 + 8) * T + c0 + 1] = acc[mt][nt][3] * scale;
        }
    }
}

__global__ __launch_bounds__(256) void score_fused(
    const float* __restrict__ q, const float* __restrict__ k,
    const float* __restrict__ p, const float* __restrict__ ub,
    const float* __restrict__ vb, float* __restrict__ cs, float* __restrict__ ps)
{
    extern __shared__ float sm[];
    float* Qu = sm;
    float* Qv = sm + 128 * QSTR;
    float* KP = sm + 2 * 128 * QSTR;

    int bh = blockIdx.z, b = bh >> 3, h = bh & 7;
    int bi = blockIdx.y * 128, bj = blockIdx.x * 128;
    int tid = threadIdx.x, warp = tid >> 5, lane = tid & 31;
    int gid = lane >> 2, tig = lane & 3;
    int wm = warp & 1, wn = warp >> 1;
    size_t obase = (size_t)bh * T * T;

    #pragma unroll
    for (int l = 0; l < 8; l++) {
        int idx = tid + l * 256;
        int row = idx >> 4, c4 = (idx & 15) * 4;
        cp16(&KP[row * QSTR + c4], &k[(size_t)((b * T + bj + row) * H + h) * DK + c4]);
    }
    cp_commit();

    #pragma unroll
    for (int l = 0; l < 8; l++) {
        int idx = tid + l * 256;
        int row = idx >> 4, c4 = (idx & 15) * 4;
        float4 vq = *(const float4*)&q[(size_t)((b * T + bi + row) * H + h) * DK + c4];
        float4 uu = *(const float4*)&ub[h * DK + c4];
        float4 vv = *(const float4*)&vb[h * DK + c4];
        Qu[row * QSTR + c4 + 0] = f2tf32(vq.x + uu.x);
        Qu[row * QSTR + c4 + 1] = f2tf32(vq.y + uu.y);
        Qu[row * QSTR + c4 + 2] = f2tf32(vq.z + uu.z);
        Qu[row * QSTR + c4 + 3] = f2tf32(vq.w + uu.w);
        Qv[row * QSTR + c4 + 0] = f2tf32(vq.x + vv.x);
        Qv[row * QSTR + c4 + 1] = f2tf32(vq.y + vv.y);
        Qv[row * QSTR + c4 + 2] = f2tf32(vq.z + vv.z);
        Qv[row * QSTR + c4 + 3] = f2tf32(vq.w + vv.w);
    }
    cp_wait0();
    __syncthreads();

    score_mma_store(Qu, KP, cs, obase, bi, bj, wm, wn, gid, tig);
    __syncthreads();

    #pragma unroll
    for (int l = 0; l < 8; l++) {
        int idx = tid + l * 256;
        int row = idx >> 4, c4 = (idx & 15) * 4;
        cp16(&KP[row * QSTR + c4], &p[(size_t)((b * T + bj + row) * H + h) * DK + c4]);
    }
    cp_commit();
    cp_wait0();
    __syncthreads();

    score_mma_store(Qv, KP, ps, obase, bi, bj, wm, wn, gid, tig);
}

// ---------------------------------------------------------------------------
// Fused rel-shift + softmax. Closed-form shift (no division):
//   shifted[i,j] = (j<=i) ? ps[i, T+j-i-1] : (j==i+1) ? 0 : ps[i+1, j-i-2]
// Output rounded to tf32 (feeds context MMA).
// ---------------------------------------------------------------------------
__global__ __launch_bounds__(256) void softmax_shift_kernel(
    const float* __restrict__ cs, const float* __restrict__ ps,
    float* __restrict__ attn)
{
    int i  = blockIdx.x;
    int bh = blockIdx.y;
    int tid = threadIdx.x;
    size_t base = (size_t)bh * T * T;

    float vals[4];
    float mx = -3.4e38f;
    #pragma unroll
    for (int l = 0; l < 4; l++) {
        int j = tid + l * 256;
        float pv;
        if (j <= i)
            pv = ps[base + (size_t)i * T + (T + j - i - 1)];
        else if (j == i + 1)
            pv = 0.0f;
        else
            pv = ps[base + (size_t)(i + 1) * T + (j - i - 2)];
        float s = cs[base + (size_t)i * T + j] + pv;
        vals[l] = s;
        mx = fmaxf(mx, s);
    }

    __shared__ float red[8];
    #pragma unroll
    for (int o = 16; o > 0; o >>= 1) mx = fmaxf(mx, __shfl_xor_sync(0xffffffffu, mx, o));
    if ((tid & 31) == 0) red[tid >> 5] = mx;
    __syncthreads();
    if (tid == 0) {
        float m = red[0];
        #pragma unroll
        for (int w = 1; w < 8; w++) m = fmaxf(m, red[w]);
        red[0] = m;
    }
    __syncthreads();
    mx = red[0];
    __syncthreads();

    float sum = 0.f;
    #pragma unroll
    for (int l = 0; l < 4; l++) { vals[l] = __expf(vals[l] - mx); sum += vals[l]; }
    #pragma unroll
    for (int o = 16; o > 0; o >>= 1) sum += __shfl_xor_sync(0xffffffffu, sum, o);
    if ((tid & 31) == 0) red[tid >> 5] = sum;
    __syncthreads();
    if (tid == 0) {
        float s = 0.f;
        #pragma unroll
        for (int w = 0; w < 8; w++) s += red[w];
        red[0] = s;
    }
    __syncthreads();
    float rinv = 1.0f / red[0];
    #pragma unroll
    for (int l = 0; l < 4; l++) {
        int j = tid + l * 256;
        attn[base + (size_t)i * T + j] = f2tf32(vals[l] * rinv);
    }
}

// ---------------------------------------------------------------------------
// Context: ctx[b,i,h,d] = sum_j attn[bh,i,j] * v[b,j,h,d]
// Block 128i x 64d, 256 thr (8 warps 4x2), K-step 16, 3-stage cp.async.
// Output rounded (feeds final GEMM).
// ---------------------------------------------------------------------------
__global__ __launch_bounds__(256, 2) void context_tc(
    const float* __restrict__ attn, const float* __restrict__ v,
    float* __restrict__ ctx)
{
    __shared__ float As[3][128][20];
    __shared__ float Bs[3][16][72];
    int bh = blockIdx.y, b = bh >> 3, h = bh & 7;
    int bm = blockIdx.x * 128;
    int tid = threadIdx.x, warp = tid >> 5, lane = tid & 31;
    int gid = lane >> 2, tig = lane & 3;
    int wm = warp >> 1, wn = warp & 1;
    int ar = tid >> 2, ac = (tid & 3) * 4;
    int br = tid >> 4, bc = (tid & 15) * 4;
    size_t abase = (size_t)bh * T * T;

    const float* Abase = attn + abase + (size_t)(bm + ar) * T + ac;
    const float* Vbase = v + (size_t)((b * T + br) * H + h) * DK + bc;
    const int nsteps = T / 16;

    #pragma unroll
    for (int s = 0; s < 2; s++) {
        int k0 = s * 16;
        cp16(&As[s][ar][ac],      Abase + k0);
        cp16(&As[s][ar + 64][ac], Abase + (size_t)64 * T + k0);
        cp16(&Bs[s][br][bc],      Vbase + (size_t)k0 * H * DK);
        cp_commit();
    }

    float acc[2][4][4] = {};
    for (int s = 0; s < nsteps; s++) {
        cp_wait1();
        __syncthreads();
        int st = s % 3;
        if (s + 2 < nsteps) {
            int k0 = (s + 2) * 16, st2 = (s + 2) % 3;
            cp16(&As[st2][ar][ac],      Abase + k0);
            cp16(&As[st2][ar + 64][ac], Abase + (size_t)64 * T + k0);
            cp16(&Bs[st2][br][bc],      Vbase + (size_t)k0 * H * DK);
        }
        cp_commit();

        #pragma unroll
        for (int k8 = 0; k8 < 2; k8++) {
            int kb = k8 * 8;
            float af[2][4], bf[4][2];
            #pragma unroll
            for (int mt = 0; mt < 2; mt++) {
                int r = wm * 32 + mt * 16 + gid;
                af[mt][0] = As[st][r][kb + tig];
                af[mt][1] = As[st][r + 8][kb + tig];
                af[mt][2] = As[st][r][kb + tig + 4];
                af[mt][3] = As[st][r + 8][kb + tig + 4];
            }
            #pragma unroll
            for (int nt = 0; nt < 4; nt++) {
                int c = wn * 32 + nt * 8 + gid;
                bf[nt][0] = Bs[st][kb + tig][c];
                bf[nt][1] = Bs[st][kb + tig + 4][c];
            }
            #pragma unroll
            for (int mt = 0; mt < 2; mt++)
                #pragma unroll
                for (int nt = 0; nt < 4; nt++)
                    mma_tf32(acc[mt][nt], af[mt], bf[nt]);
        }
    }

    #pragma unroll
    for (int mt = 0; mt < 2; mt++) {
        int r0 = bm + wm * 32 + mt * 16 + gid;
        #pragma unroll
        for (int nt = 0; nt < 4; nt++) {
            int c0 = wn * 32 + nt * 8 + 2 * tig;
            ctx[(size_t)((b * T + r0) * H + h) * DK + c0]         = f2tf32(acc[mt][nt][0]);
            ctx[(size_t)((b * T + r0) * H + h) * DK + c0 + 1]     = f2tf32(acc[mt][nt][1]);
            ctx[(size_t)((b * T + r0 + 8) * H + h) * DK + c0]     = f2tf32(acc[mt][nt][2]);
            ctx[(size_t)((b * T + r0 + 8) * H + h) * DK + c0 + 1] = f2tf32(acc[mt][nt][3]);
        }
    }
}

// ---------------------------------------------------------------------------
extern "C" void kernel_launch(void* const* d_in, const int* in_sizes, int n_in,
                              void* d_out, int out_size)
{
    const float* query = (const float*)d_in[0];
    const float* key   = (const float*)d_in[1];
    const float* value = (const float*)d_in[2];
    const float* pos   = (const float*)d_in[3];
    const float* Wq = (const float*)d_in[4];
    const float* bq = (const float*)d_in[5];
    const float* Wk = (const float*)d_in[6];
    const float* bk = (const float*)d_in[7];
    const float* Wv = (const float*)d_in[8];
    const float* bv = (const float*)d_in[9];
    const float* Wp = (const float*)d_in[10];
    const float* ub = (const float*)d_in[11];
    const float* vb = (const float*)d_in[12];
    const float* Wo = (const float*)d_in[13];
    const float* bo = (const float*)d_in[14];
    float* out = (float*)d_out;

    float *q, *k, *v, *p, *xq, *xk, *xv, *xp, *w, *cs, *ps, *ctx;
    cudaGetSymbolAddress((void**)&q,   g_q);
    cudaGetSymbolAddress((void**)&k,   g_k);
    cudaGetSymbolAddress((void**)&v,   g_v);
    cudaGetSymbolAddress((void**)&p,   g_p);
    cudaGetSymbolAddress((void**)&xq,  g_xq);
    cudaGetSymbolAddress((void**)&xk,  g_xk);
    cudaGetSymbolAddress((void**)&xv,  g_xv);
    cudaGetSymbolAddress((void**)&xp,  g_xp);
    cudaGetSymbolAddress((void**)&w,   g_w);
    cudaGetSymbolAddress((void**)&cs,  g_cs);
    cudaGetSymbolAddress((void**)&ps,  g_ps);
    cudaGetSymbolAddress((void**)&ctx, g_ctx);

    const int SMEM_GEMM  = (3 * 128 * 20 + 3 * 16 * 136) * 4;   // 56832 B
    const int SMEM_SCORE = 3 * 128 * QSTR * 4;                  // 104448 B
    cudaFuncSetAttribute(sgemm_bias_tc,
        cudaFuncAttributeMaxDynamicSharedMemorySize, SMEM_GEMM);
    cudaFuncSetAttribute(score_fused,
        cudaFuncAttributeMaxDynamicSharedMemorySize, SMEM_SCORE);

    // Pre-round inputs + weights to tf32 (removes truncation bias from MMA loads)
    const int ACT4 = BT * D / 4, W4 = D * D / 4;
    round_pass<<<(ACT4 + 255) / 256, 256>>>(query, xq, ACT4);
    round_pass<<<(ACT4 + 255) / 256, 256>>>(key,   xk, ACT4);
    round_pass<<<(ACT4 + 255) / 256, 256>>>(value, xv, ACT4);
    round_pass<<<(ACT4 + 255) / 256, 256>>>(pos,   xp, ACT4);
    round_pass<<<(W4 + 255) / 256, 256>>>(Wq, w + 0 * D * D, W4);
    round_pass<<<(W4 + 255) / 256, 256>>>(Wk, w + 1 * D * D, W4);
    round_pass<<<(W4 + 255) / 256, 256>>>(Wv, w + 2 * D * D, W4);
    round_pass<<<(W4 + 255) / 256, 256>>>(Wp, w + 3 * D * D, W4);
    round_pass<<<(W4 + 255) / 256, 256>>>(Wo, w + 4 * D * D, W4);

    dim3 gproj(D / 128, BT / 128);          // (4, 64)
    sgemm_bias_tc<<<gproj, 128, SMEM_GEMM>>>(xq, w + 0 * D * D, bq, q, BT, D, D, 1);
    sgemm_bias_tc<<<gproj, 128, SMEM_GEMM>>>(xk, w + 1 * D * D, bk, k, BT, D, D, 1);
    sgemm_bias_tc<<<gproj, 128, SMEM_GEMM>>>(xv, w + 2 * D * D, bv, v, BT, D, D, 1);
    sgemm_bias_tc<<<gproj, 128, SMEM_GEMM>>>(xp, w + 3 * D * D, nullptr, p, BT, D, D, 1);

    dim3 gsc(T / 128, T / 128, B * H);      // (8, 8, 64)
    score_fused<<<gsc, 256, SMEM_SCORE>>>(q, k, p, ub, vb, cs, ps);

    dim3 gsm(T, B * H);                     // (1024, 64)
    softmax_shift_kernel<<<gsm, 256>>>(cs, ps, cs);

    dim3 gctx(T / 128, B * H);              // (8, 64)
    context_tc<<<gctx, 256>>>(cs, v, ctx);

    sgemm_bias_tc<<<gproj, 128, SMEM_GEMM>>>(ctx, w + 4 * D * D, bo, out, BT, D, D, 0);
}

// round 7
// speedup vs baseline: 1.6672x; 1.2272x over previous
#include <cuda_runtime.h>
#include <cuda_bf16.h>

#define B 8
#define T 1024
#define D 512
#define H 8
#define DK 64
#define BT (B*T)   // 8192

// Scratch (static device globals — no runtime allocation)
__device__ float g_q[BT * D];
__device__ float g_k[BT * D];
__device__ float g_v[BT * D];
__device__ float g_p[BT * D];
__device__ __nv_bfloat16 g_cs[(size_t)B * H * T * T];
__device__ __nv_bfloat16 g_ps[(size_t)B * H * T * T];
__device__ float g_attn[(size_t)B * H * T * T];
__device__ float g_ctx[BT * D];

__device__ __forceinline__ float f2tf32(float f) {
    unsigned u;
    asm("cvt.rna.tf32.f32 %0, %1;" : "=r"(u) : "f"(f));
    return __uint_as_float(u);
}

// mma.sync m16n8k8 tf32 row.col
__device__ __forceinline__ void mma_tf32(float* c, const float* a, const float* b) {
    asm volatile(
        "mma.sync.aligned.m16n8k8.row.col.f32.tf32.tf32.f32 "
        "{%0,%1,%2,%3}, {%4,%5,%6,%7}, {%8,%9}, {%0,%1,%2,%3};"
        : "+f"(c[0]), "+f"(c[1]), "+f"(c[2]), "+f"(c[3])
        : "r"(__float_as_uint(a[0])), "r"(__float_as_uint(a[1])),
          "r"(__float_as_uint(a[2])), "r"(__float_as_uint(a[3])),
          "r"(__float_as_uint(b[0])), "r"(__float_as_uint(b[1])));
}

__device__ __forceinline__ void cp16(float* dst, const float* src) {
    unsigned d = (unsigned)__cvta_generic_to_shared(dst);
    asm volatile("cp.async.ca.shared.global [%0], [%1], 16;" :: "r"(d), "l"(src));
}
__device__ __forceinline__ void cp_commit() { asm volatile("cp.async.commit_group;"); }
__device__ __forceinline__ void cp_wait1()  { asm volatile("cp.async.wait_group 1;"); }
__device__ __forceinline__ void cp_wait0()  { asm volatile("cp.async.wait_group 0;"); }

// ---------------------------------------------------------------------------
// GEMM: C[M,N] = A[M,K] @ W[K,N] (+bias). Block 128x128, 256 thr (8 warps 2x4),
// warp 64x32, K-step 16, register-staged double buffer, rounded tf32 at store.
// round_out: round epilogue to tf32 so downstream truncating loads are exact.
// ---------------------------------------------------------------------------
__global__ __launch_bounds__(256) void sgemm_bias_tc(
    const float* __restrict__ A, const float* __restrict__ W,
    const float* __restrict__ bias, float* __restrict__ C,
    int M, int N, int K, int round_out)
{
    __shared__ float As[2][128][20];
    __shared__ float Bs[2][16][136];
    int tid = threadIdx.x, warp = tid >> 5, lane = tid & 31;
    int gid = lane >> 2, tig = lane & 3;
    int wm = warp & 1, wn = warp >> 1;
    int bm = blockIdx.y * 128, bn = blockIdx.x * 128;
    int arow = tid >> 2, ac4 = (tid & 3) * 4;
    int brow = tid >> 5, bc4 = (tid & 31) * 4;

    const float* Ap0 = A + (size_t)(bm + arow) * K + ac4;
    const float* Ap1 = A + (size_t)(bm + arow + 64) * K + ac4;
    const float* Wp0 = W + (size_t)brow * N + bn + bc4;
    const float* Wp1 = W + (size_t)(brow + 8) * N + bn + bc4;

    float4 sa0 = *(const float4*)Ap0;
    float4 sa1 = *(const float4*)Ap1;
    float4 sb0 = *(const float4*)Wp0;
    float4 sb1 = *(const float4*)Wp1;

    float acc[4][4][4] = {};
    int nsteps = K / 16;
    for (int s = 0; s < nsteps; s++) {
        int buf = s & 1;
        As[buf][arow][ac4+0] = f2tf32(sa0.x); As[buf][arow][ac4+1] = f2tf32(sa0.y);
        As[buf][arow][ac4+2] = f2tf32(sa0.z); As[buf][arow][ac4+3] = f2tf32(sa0.w);
        As[buf][arow+64][ac4+0] = f2tf32(sa1.x); As[buf][arow+64][ac4+1] = f2tf32(sa1.y);
        As[buf][arow+64][ac4+2] = f2tf32(sa1.z); As[buf][arow+64][ac4+3] = f2tf32(sa1.w);
        Bs[buf][brow][bc4+0] = f2tf32(sb0.x); Bs[buf][brow][bc4+1] = f2tf32(sb0.y);
        Bs[buf][brow][bc4+2] = f2tf32(sb0.z); Bs[buf][brow][bc4+3] = f2tf32(sb0.w);
        Bs[buf][brow+8][bc4+0] = f2tf32(sb1.x); Bs[buf][brow+8][bc4+1] = f2tf32(sb1.y);
        Bs[buf][brow+8][bc4+2] = f2tf32(sb1.z); Bs[buf][brow+8][bc4+3] = f2tf32(sb1.w);
        __syncthreads();

        if (s + 1 < nsteps) {
            int k0 = (s + 1) * 16;
            sa0 = *(const float4*)(Ap0 + k0);
            sa1 = *(const float4*)(Ap1 + k0);
            sb0 = *(const float4*)(Wp0 + (size_t)k0 * N);
            sb1 = *(const float4*)(Wp1 + (size_t)k0 * N);
        }

        #pragma unroll
        for (int k8 = 0; k8 < 2; k8++) {
            int kb = k8 * 8;
            float af[4][4], bf[4][2];
            #pragma unroll
            for (int mt = 0; mt < 4; mt++) {
                int r = wm * 64 + mt * 16 + gid;
                af[mt][0] = As[buf][r][kb + tig];
                af[mt][1] = As[buf][r + 8][kb + tig];
                af[mt][2] = As[buf][r][kb + tig + 4];
                af[mt][3] = As[buf][r + 8][kb + tig + 4];
            }
            #pragma unroll
            for (int nt = 0; nt < 4; nt++) {
                int c = wn * 32 + nt * 8 + gid;
                bf[nt][0] = Bs[buf][kb + tig][c];
                bf[nt][1] = Bs[buf][kb + tig + 4][c];
            }
            #pragma unroll
            for (int mt = 0; mt < 4; mt++)
                #pragma unroll
                for (int nt = 0; nt < 4; nt++)
                    mma_tf32(acc[mt][nt], af[mt], bf[nt]);
        }
        __syncthreads();
    }

    #pragma unroll
    for (int mt = 0; mt < 4; mt++) {
        int r0 = bm + wm * 64 + mt * 16 + gid;
        #pragma unroll
        for (int nt = 0; nt < 4; nt++) {
            int c0 = bn + wn * 32 + nt * 8 + 2 * tig;
            float b0 = bias ? bias[c0] : 0.f;
            float b1 = bias ? bias[c0 + 1] : 0.f;
            float v0 = acc[mt][nt][0] + b0, v1 = acc[mt][nt][1] + b1;
            float v2 = acc[mt][nt][2] + b0, v3 = acc[mt][nt][3] + b1;
            if (round_out) {
                v0 = f2tf32(v0); v1 = f2tf32(v1);
                v2 = f2tf32(v2); v3 = f2tf32(v3);
            }
            C[(size_t)r0 * N + c0]           = v0;
            C[(size_t)r0 * N + c0 + 1]       = v1;
            C[(size_t)(r0 + 8) * N + c0]     = v2;
            C[(size_t)(r0 + 8) * N + c0 + 1] = v3;
        }
    }
}

// ---------------------------------------------------------------------------
// Fused scores -> bf16: cs = scale*(q+u)·k, ps = scale*(q+v)·p (128x128 tiles).
// ---------------------------------------------------------------------------
#define QSTR 68
__device__ __forceinline__ void score_mma_store(
    const float* __restrict__ Q, const float* __restrict__ KP,
    __nv_bfloat16* __restrict__ out, size_t obase, int bi, int bj,
    int wm, int wn, int gid, int tig)
{
    float acc[4][4][4] = {};
    #pragma unroll
    for (int k8 = 0; k8 < 8; k8++) {
        int kb = k8 * 8;
        float af[4][4], bf[4][2];
        #pragma unroll
        for (int mt = 0; mt < 4; mt++) {
            int r = wm * 64 + mt * 16 + gid;
            af[mt][0] = Q[r * QSTR + kb + tig];
            af[mt][1] = Q[(r + 8) * QSTR + kb + tig];
            af[mt][2] = Q[r * QSTR + kb + tig + 4];
            af[mt][3] = Q[(r + 8) * QSTR + kb + tig + 4];
        }
        #pragma unroll
        for (int nt = 0; nt < 4; nt++) {
            int c = wn * 32 + nt * 8 + gid;
            bf[nt][0] = KP[c * QSTR + kb + tig];
            bf[nt][1] = KP[c * QSTR + kb + tig + 4];
        }
        #pragma unroll
        for (int mt = 0; mt < 4; mt++)
            #pragma unroll
            for (int nt = 0; nt < 4; nt++)
                mma_tf32(acc[mt][nt], af[mt], bf[nt]);
    }
    const float scale = 0.04419417382415922f;   // 1/sqrt(512)
    #pragma unroll
    for (int mt = 0; mt < 4; mt++) {
        int r0 = bi + wm * 64 + mt * 16 + gid;
        #pragma unroll
        for (int nt = 0; nt < 4; nt++) {
            int c0 = bj + wn * 32 + nt * 8 + 2 * tig;
            __nv_bfloat162 p0 = __floats2bfloat162_rn(acc[mt][nt][0] * scale,
                                                      acc[mt][nt][1] * scale);
            __nv_bfloat162 p1 = __floats2bfloat162_rn(acc[mt][nt][2] * scale,
                                                      acc[mt][nt][3] * scale);
            *(__nv_bfloat162*)&out[obase + (size_t)r0 * T + c0]       = p0;
            *(__nv_bfloat162*)&out[obase + (size_t)(r0 + 8) * T + c0] = p1;
        }
    }
}

__global__ __launch_bounds__(256) void score_fused(
    const float* __restrict__ q, const float* __restrict__ k,
    const float* __restrict__ p, const float* __restrict__ ub,
    const float* __restrict__ vb,
    __nv_bfloat16* __restrict__ cs, __nv_bfloat16* __restrict__ ps)
{
    extern __shared__ float sm[];
    float* Qu = sm;
    float* Qv = sm + 128 * QSTR;
    float* KP = sm + 2 * 128 * QSTR;

    int bh = blockIdx.z, b = bh >> 3, h = bh & 7;
    int bi = blockIdx.y * 128, bj = blockIdx.x * 128;
    int tid = threadIdx.x, warp = tid >> 5, lane = tid & 31;
    int gid = lane >> 2, tig = lane & 3;
    int wm = warp & 1, wn = warp >> 1;
    size_t obase = (size_t)bh * T * T;

    #pragma unroll
    for (int l = 0; l < 8; l++) {
        int idx = tid + l * 256;
        int row = idx >> 4, c4 = (idx & 15) * 4;
        cp16(&KP[row * QSTR + c4], &k[(size_t)((b * T + bj + row) * H + h) * DK + c4]);
    }
    cp_commit();

    #pragma unroll
    for (int l = 0; l < 8; l++) {
        int idx = tid + l * 256;
        int row = idx >> 4, c4 = (idx & 15) * 4;
        float4 vq = *(const float4*)&q[(size_t)((b * T + bi + row) * H + h) * DK + c4];
        float4 uu = *(const float4*)&ub[h * DK + c4];
        float4 vv = *(const float4*)&vb[h * DK + c4];
        Qu[row * QSTR + c4 + 0] = f2tf32(vq.x + uu.x);
        Qu[row * QSTR + c4 + 1] = f2tf32(vq.y + uu.y);
        Qu[row * QSTR + c4 + 2] = f2tf32(vq.z + uu.z);
        Qu[row * QSTR + c4 + 3] = f2tf32(vq.w + uu.w);
        Qv[row * QSTR + c4 + 0] = f2tf32(vq.x + vv.x);
        Qv[row * QSTR + c4 + 1] = f2tf32(vq.y + vv.y);
        Qv[row * QSTR + c4 + 2] = f2tf32(vq.z + vv.z);
        Qv[row * QSTR + c4 + 3] = f2tf32(vq.w + vv.w);
    }
    cp_wait0();
    __syncthreads();

    score_mma_store(Qu, KP, cs, obase, bi, bj, wm, wn, gid, tig);
    __syncthreads();

    #pragma unroll
    for (int l = 0; l < 8; l++) {
        int idx = tid + l * 256;
        int row = idx >> 4, c4 = (idx & 15) * 4;
        cp16(&KP[row * QSTR + c4], &p[(size_t)((b * T + bj + row) * H + h) * DK + c4]);
    }
    cp_commit();
    cp_wait0();
    __syncthreads();

    score_mma_store(Qv, KP, ps, obase, bi, bj, wm, wn, gid, tig);
}

// ---------------------------------------------------------------------------
// Fused rel-shift + softmax. bf16 in, tf32-rounded fp32 out.
//   shifted[i,j] = (j<=i) ? ps[i, T+j-i-1] : (j==i+1) ? 0 : ps[i+1, j-i-2]
// ---------------------------------------------------------------------------
__global__ __launch_bounds__(256) void softmax_shift_kernel(
    const __nv_bfloat16* __restrict__ cs, const __nv_bfloat16* __restrict__ ps,
    float* __restrict__ attn)
{
    int i  = blockIdx.x;
    int bh = blockIdx.y;
    int tid = threadIdx.x;
    size_t base = (size_t)bh * T * T;

    float vals[4];
    float mx = -3.4e38f;
    #pragma unroll
    for (int l = 0; l < 4; l++) {
        int j = tid + l * 256;
        float pv;
        if (j <= i)
            pv = __bfloat162float(ps[base + (size_t)i * T + (T + j - i - 1)]);
        else if (j == i + 1)
            pv = 0.0f;
        else
            pv = __bfloat162float(ps[base + (size_t)(i + 1) * T + (j - i - 2)]);
        float s = __bfloat162float(cs[base + (size_t)i * T + j]) + pv;
        vals[l] = s;
        mx = fmaxf(mx, s);
    }

    __shared__ float red[8];
    #pragma unroll
    for (int o = 16; o > 0; o >>= 1) mx = fmaxf(mx, __shfl_xor_sync(0xffffffffu, mx, o));
    if ((tid & 31) == 0) red[tid >> 5] = mx;
    __syncthreads();
    if (tid == 0) {
        float m = red[0];
        #pragma unroll
        for (int w = 1; w < 8; w++) m = fmaxf(m, red[w]);
        red[0] = m;
    }
    __syncthreads();
    mx = red[0];
    __syncthreads();

    float sum = 0.f;
    #pragma unroll
    for (int l = 0; l < 4; l++) { vals[l] = __expf(vals[l] - mx); sum += vals[l]; }
    #pragma unroll
    for (int o = 16; o > 0; o >>= 1) sum += __shfl_xor_sync(0xffffffffu, sum, o);
    if ((tid & 31) == 0) red[tid >> 5] = sum;
    __syncthreads();
    if (tid == 0) {
        float s = 0.f;
        #pragma unroll
        for (int w = 0; w < 8; w++) s += red[w];
        red[0] = s;
    }
    __syncthreads();
    float rinv = 1.0f / red[0];
    #pragma unroll
    for (int l = 0; l < 4; l++) {
        int j = tid + l * 256;
        attn[base + (size_t)i * T + j] = f2tf32(vals[l] * rinv);
    }
}

// ---------------------------------------------------------------------------
// Context: ctx[b,i,h,d] = sum_j attn[bh,i,j] * v[b,j,h,d]
// Block 128i x 64d, 256 thr (8 warps 4x2), K-step 16, 3-stage cp.async.
// attn/v are pre-rounded -> truncating loads are exact.
// ---------------------------------------------------------------------------
__global__ __launch_bounds__(256, 2) void context_tc(
    const float* __restrict__ attn, const float* __restrict__ v,
    float* __restrict__ ctx)
{
    __shared__ float As[3][128][20];
    __shared__ float Bs[3][16][72];
    int bh = blockIdx.y, b = bh >> 3, h = bh & 7;
    int bm = blockIdx.x * 128;
    int tid = threadIdx.x, warp = tid >> 5, lane = tid & 31;
    int gid = lane >> 2, tig = lane & 3;
    int wm = warp >> 1, wn = warp & 1;
    int ar = tid >> 2, ac = (tid & 3) * 4;
    int br = tid >> 4, bc = (tid & 15) * 4;
    size_t abase = (size_t)bh * T * T;

    const float* Abase = attn + abase + (size_t)(bm + ar) * T + ac;
    const float* Vbase = v + (size_t)((b * T + br) * H + h) * DK + bc;
    const int nsteps = T / 16;

    #pragma unroll
    for (int s = 0; s < 2; s++) {
        int k0 = s * 16;
        cp16(&As[s][ar][ac],      Abase + k0);
        cp16(&As[s][ar + 64][ac], Abase + (size_t)64 * T + k0);
        cp16(&Bs[s][br][bc],      Vbase + (size_t)k0 * H * DK);
        cp_commit();
    }

    float acc[2][4][4] = {};
    for (int s = 0; s < nsteps; s++) {
        cp_wait1();
        __syncthreads();
        int st = s % 3;
        if (s + 2 < nsteps) {
            int k0 = (s + 2) * 16, st2 = (s + 2) % 3;
            cp16(&As[st2][ar][ac],      Abase + k0);
            cp16(&As[st2][ar + 64][ac], Abase + (size_t)64 * T + k0);
            cp16(&Bs[st2][br][bc],      Vbase + (size_t)k0 * H * DK);
        }
        cp_commit();

        #pragma unroll
        for (int k8 = 0; k8 < 2; k8++) {
            int kb = k8 * 8;
            float af[2][4], bf[4][2];
            #pragma unroll
            for (int mt = 0; mt < 2; mt++) {
                int r = wm * 32 + mt * 16 + gid;
                af[mt][0] = As[st][r][kb + tig];
                af[mt][1] = As[st][r + 8][kb + tig];
                af[mt][2] = As[st][r][kb + tig + 4];
                af[mt][3] = As[st][r + 8][kb + tig + 4];
            }
            #pragma unroll
            for (int nt = 0; nt < 4; nt++) {
                int c = wn * 32 + nt * 8 + gid;
                bf[nt][0] = Bs[st][kb + tig][c];
                bf[nt][1] = Bs[st][kb + tig + 4][c];
            }
            #pragma unroll
            for (int mt = 0; mt < 2; mt++)
                #pragma unroll
                for (int nt = 0; nt < 4; nt++)
                    mma_tf32(acc[mt][nt], af[mt], bf[nt]);
        }
    }

    #pragma unroll
    for (int mt = 0; mt < 2; mt++) {
        int r0 = bm + wm * 32 + mt * 16 + gid;
        #pragma unroll
        for (int nt = 0; nt < 4; nt++) {
            int c0 = wn * 32 + nt * 8 + 2 * tig;
            ctx[(size_t)((b * T + r0) * H + h) * DK + c0]         = acc[mt][nt][0];
            ctx[(size_t)((b * T + r0) * H + h) * DK + c0 + 1]     = acc[mt][nt][1];
            ctx[(size_t)((b * T + r0 + 8) * H + h) * DK + c0]     = acc[mt][nt][2];
            ctx[(size_t)((b * T + r0 + 8) * H + h) * DK + c0 + 1] = acc[mt][nt][3];
        }
    }
}

// ---------------------------------------------------------------------------
extern "C" void kernel_launch(void* const* d_in, const int* in_sizes, int n_in,
                              void* d_out, int out_size)
{
    const float* query = (const float*)d_in[0];
    const float* key   = (const float*)d_in[1];
    const float* value = (const float*)d_in[2];
    const float* pos   = (const float*)d_in[3];
    const float* Wq = (const float*)d_in[4];
    const float* bq = (const float*)d_in[5];
    const float* Wk = (const float*)d_in[6];
    const float* bk = (const float*)d_in[7];
    const float* Wv = (const float*)d_in[8];
    const float* bv = (const float*)d_in[9];
    const float* Wp = (const float*)d_in[10];
    const float* ub = (const float*)d_in[11];
    const float* vb = (const float*)d_in[12];
    const float* Wo = (const float*)d_in[13];
    const float* bo = (const float*)d_in[14];
    float* out = (float*)d_out;

    float *q, *k, *v, *p, *attn, *ctx;
    __nv_bfloat16 *cs, *ps;
    cudaGetSymbolAddress((void**)&q,    g_q);
    cudaGetSymbolAddress((void**)&k,    g_k);
    cudaGetSymbolAddress((void**)&v,    g_v);
    cudaGetSymbolAddress((void**)&p,    g_p);
    cudaGetSymbolAddress((void**)&cs,   g_cs);
    cudaGetSymbolAddress((void**)&ps,   g_ps);
    cudaGetSymbolAddress((void**)&attn, g_attn);
    cudaGetSymbolAddress((void**)&ctx,  g_ctx);

    const int SMEM_SCORE = 3 * 128 * QSTR * 4;   // 104448 B
    cudaFuncSetAttribute(score_fused,
        cudaFuncAttributeMaxDynamicSharedMemorySize, SMEM_SCORE);

    dim3 gproj(D / 128, BT / 128);          // (4, 64)
    sgemm_bias_tc<<<gproj, 256>>>(query, Wq, bq, q, BT, D, D, 1);
    sgemm_bias_tc<<<gproj, 256>>>(key,   Wk, bk, k, BT, D, D, 1);
    sgemm_bias_tc<<<gproj, 256>>>(value, Wv, bv, v, BT, D, D, 1);
    sgemm_bias_tc<<<gproj, 256>>>(pos,   Wp, nullptr, p, BT, D, D, 1);

    dim3 gsc(T / 128, T / 128, B * H);      // (8, 8, 64)
    score_fused<<<gsc, 256, SMEM_SCORE>>>(q, k, p, ub, vb, cs, ps);

    dim3 gsm(T, B * H);                     // (1024, 64)
    softmax_shift_kernel<<<gsm, 256>>>(cs, ps, attn);

    dim3 gctx(T / 128, B * H);              // (8, 64)
    context_tc<<<gctx, 256>>>(attn, v, ctx);

    sgemm_bias_tc<<<gproj, 256>>>(ctx, Wo, bo, out, BT, D, D, 0);
}

// round 8
// speedup vs baseline: 1.6891x; 1.0131x over previous
#include <cuda_runtime.h>
#include <cuda_bf16.h>

#define B 8
#define T 1024
#define D 512
#define H 8
#define DK 64
#define BT (B*T)   // 8192

// Scratch (static device globals — no runtime allocation)
__device__ float g_q[BT * D];
__device__ float g_k[BT * D];
__device__ float g_v[BT * D];
__device__ float g_p[BT * D];
__device__ __nv_bfloat16 g_cs[(size_t)B * H * T * T];
__device__ __nv_bfloat16 g_ps[(size_t)B * H * T * T];
__device__ float g_attn[(size_t)B * H * T * T];
__device__ float g_ctx[BT * D];

__device__ __forceinline__ float f2tf32(float f) {
    unsigned u;
    asm("cvt.rna.tf32.f32 %0, %1;" : "=r"(u) : "f"(f));
    return __uint_as_float(u);
}

// mma.sync m16n8k8 tf32 row.col
__device__ __forceinline__ void mma_tf32(float* c, const float* a, const float* b) {
    asm volatile(
        "mma.sync.aligned.m16n8k8.row.col.f32.tf32.tf32.f32 "
        "{%0,%1,%2,%3}, {%4,%5,%6,%7}, {%8,%9}, {%0,%1,%2,%3};"
        : "+f"(c[0]), "+f"(c[1]), "+f"(c[2]), "+f"(c[3])
        : "r"(__float_as_uint(a[0])), "r"(__float_as_uint(a[1])),
          "r"(__float_as_uint(a[2])), "r"(__float_as_uint(a[3])),
          "r"(__float_as_uint(b[0])), "r"(__float_as_uint(b[1])));
}

__device__ __forceinline__ void cp16(float* dst, const float* src) {
    unsigned d = (unsigned)__cvta_generic_to_shared(dst);
    asm volatile("cp.async.ca.shared.global [%0], [%1], 16;" :: "r"(d), "l"(src));
}
__device__ __forceinline__ void cp_commit() { asm volatile("cp.async.commit_group;"); }
__device__ __forceinline__ void cp_wait1()  { asm volatile("cp.async.wait_group 1;"); }
__device__ __forceinline__ void cp_wait0()  { asm volatile("cp.async.wait_group 0;"); }

// ---------------------------------------------------------------------------
// GEMM: C[M,N] = A[M,K] @ W[K,N] (+bias). Block 128x128, 256 thr (8 warps 2x4),
// warp 64x32, K-step 16, register-staged double buffer, rounded tf32 at store.
// round_out: round epilogue to tf32 so downstream truncating loads are exact.
// ---------------------------------------------------------------------------
__global__ __launch_bounds__(256) void sgemm_bias_tc(
    const float* __restrict__ A, const float* __restrict__ W,
    const float* __restrict__ bias, float* __restrict__ C,
    int M, int N, int K, int round_out)
{
    __shared__ float As[2][128][20];
    __shared__ float Bs[2][16][136];
    int tid = threadIdx.x, warp = tid >> 5, lane = tid & 31;
    int gid = lane >> 2, tig = lane & 3;
    int wm = warp & 1, wn = warp >> 1;
    int bm = blockIdx.y * 128, bn = blockIdx.x * 128;
    int arow = tid >> 2, ac4 = (tid & 3) * 4;
    int brow = tid >> 5, bc4 = (tid & 31) * 4;

    const float* Ap0 = A + (size_t)(bm + arow) * K + ac4;
    const float* Ap1 = A + (size_t)(bm + arow + 64) * K + ac4;
    const float* Wp0 = W + (size_t)brow * N + bn + bc4;
    const float* Wp1 = W + (size_t)(brow + 8) * N + bn + bc4;

    float4 sa0 = *(const float4*)Ap0;
    float4 sa1 = *(const float4*)Ap1;
    float4 sb0 = *(const float4*)Wp0;
    float4 sb1 = *(const float4*)Wp1;

    float acc[4][4][4] = {};
    int nsteps = K / 16;
    for (int s = 0; s < nsteps; s++) {
        int buf = s & 1;
        As[buf][arow][ac4+0] = f2tf32(sa0.x); As[buf][arow][ac4+1] = f2tf32(sa0.y);
        As[buf][arow][ac4+2] = f2tf32(sa0.z); As[buf][arow][ac4+3] = f2tf32(sa0.w);
        As[buf][arow+64][ac4+0] = f2tf32(sa1.x); As[buf][arow+64][ac4+1] = f2tf32(sa1.y);
        As[buf][arow+64][ac4+2] = f2tf32(sa1.z); As[buf][arow+64][ac4+3] = f2tf32(sa1.w);
        Bs[buf][brow][bc4+0] = f2tf32(sb0.x); Bs[buf][brow][bc4+1] = f2tf32(sb0.y);
        Bs[buf][brow][bc4+2] = f2tf32(sb0.z); Bs[buf][brow][bc4+3] = f2tf32(sb0.w);
        Bs[buf][brow+8][bc4+0] = f2tf32(sb1.x); Bs[buf][brow+8][bc4+1] = f2tf32(sb1.y);
        Bs[buf][brow+8][bc4+2] = f2tf32(sb1.z); Bs[buf][brow+8][bc4+3] = f2tf32(sb1.w);
        __syncthreads();

        if (s + 1 < nsteps) {
            int k0 = (s + 1) * 16;
            sa0 = *(const float4*)(Ap0 + k0);
            sa1 = *(const float4*)(Ap1 + k0);
            sb0 = *(const float4*)(Wp0 + (size_t)k0 * N);
            sb1 = *(const float4*)(Wp1 + (size_t)k0 * N);
        }

        #pragma unroll
        for (int k8 = 0; k8 < 2; k8++) {
            int kb = k8 * 8;
            float af[4][4], bf[4][2];
            #pragma unroll
            for (int mt = 0; mt < 4; mt++) {
                int r = wm * 64 + mt * 16 + gid;
                af[mt][0] = As[buf][r][kb + tig];
                af[mt][1] = As[buf][r + 8][kb + tig];
                af[mt][2] = As[buf][r][kb + tig + 4];
                af[mt][3] = As[buf][r + 8][kb + tig + 4];
            }
            #pragma unroll
            for (int nt = 0; nt < 4; nt++) {
                int c = wn * 32 + nt * 8 + gid;
                bf[nt][0] = Bs[buf][kb + tig][c];
                bf[nt][1] = Bs[buf][kb + tig + 4][c];
            }
            #pragma unroll
            for (int mt = 0; mt < 4; mt++)
                #pragma unroll
                for (int nt = 0; nt < 4; nt++)
                    mma_tf32(acc[mt][nt], af[mt], bf[nt]);
        }
        __syncthreads();
    }

    #pragma unroll
    for (int mt = 0; mt < 4; mt++) {
        int r0 = bm + wm * 64 + mt * 16 + gid;
        #pragma unroll
        for (int nt = 0; nt < 4; nt++) {
            int c0 = bn + wn * 32 + nt * 8 + 2 * tig;
            float b0 = bias ? bias[c0] : 0.f;
            float b1 = bias ? bias[c0 + 1] : 0.f;
            float v0 = acc[mt][nt][0] + b0, v1 = acc[mt][nt][1] + b1;
            float v2 = acc[mt][nt][2] + b0, v3 = acc[mt][nt][3] + b1;
            if (round_out) {
                v0 = f2tf32(v0); v1 = f2tf32(v1);
                v2 = f2tf32(v2); v3 = f2tf32(v3);
            }
            C[(size_t)r0 * N + c0]           = v0;
            C[(size_t)r0 * N + c0 + 1]       = v1;
            C[(size_t)(r0 + 8) * N + c0]     = v2;
            C[(size_t)(r0 + 8) * N + c0 + 1] = v3;
        }
    }
}

// ---------------------------------------------------------------------------
// Fused scores -> bf16: cs = scale*(q+u)·k, ps = scale*(q+v)·p (128x128 tiles).
// ---------------------------------------------------------------------------
#define QSTR 68
__device__ __forceinline__ void score_mma_store(
    const float* __restrict__ Q, const float* __restrict__ KP,
    __nv_bfloat16* __restrict__ out, size_t obase, int bi, int bj,
    int wm, int wn, int gid, int tig)
{
    float acc[4][4][4] = {};
    #pragma unroll
    for (int k8 = 0; k8 < 8; k8++) {
        int kb = k8 * 8;
        float af[4][4], bf[4][2];
        #pragma unroll
        for (int mt = 0; mt < 4; mt++) {
            int r = wm * 64 + mt * 16 + gid;
            af[mt][0] = Q[r * QSTR + kb + tig];
            af[mt][1] = Q[(r + 8) * QSTR + kb + tig];
            af[mt][2] = Q[r * QSTR + kb + tig + 4];
            af[mt][3] = Q[(r + 8) * QSTR + kb + tig + 4];
        }
        #pragma unroll
        for (int nt = 0; nt < 4; nt++) {
            int c = wn * 32 + nt * 8 + gid;
            bf[nt][0] = KP[c * QSTR + kb + tig];
            bf[nt][1] = KP[c * QSTR + kb + tig + 4];
        }
        #pragma unroll
        for (int mt = 0; mt < 4; mt++)
            #pragma unroll
            for (int nt = 0; nt < 4; nt++)
                mma_tf32(acc[mt][nt], af[mt], bf[nt]);
    }
    const float scale = 0.04419417382415922f;   // 1/sqrt(512)
    #pragma unroll
    for (int mt = 0; mt < 4; mt++) {
        int r0 = bi + wm * 64 + mt * 16 + gid;
        #pragma unroll
        for (int nt = 0; nt < 4; nt++) {
            int c0 = bj + wn * 32 + nt * 8 + 2 * tig;
            __nv_bfloat162 p0 = __floats2bfloat162_rn(acc[mt][nt][0] * scale,
                                                      acc[mt][nt][1] * scale);
            __nv_bfloat162 p1 = __floats2bfloat162_rn(acc[mt][nt][2] * scale,
                                                      acc[mt][nt][3] * scale);
            *(__nv_bfloat162*)&out[obase + (size_t)r0 * T + c0]       = p0;
            *(__nv_bfloat162*)&out[obase + (size_t)(r0 + 8) * T + c0] = p1;
        }
    }
}

__global__ __launch_bounds__(256) void score_fused(
    const float* __restrict__ q, const float* __restrict__ k,
    const float* __restrict__ p, const float* __restrict__ ub,
    const float* __restrict__ vb,
    __nv_bfloat16* __restrict__ cs, __nv_bfloat16* __restrict__ ps)
{
    extern __shared__ float sm[];
    float* Qu = sm;
    float* Qv = sm + 128 * QSTR;
    float* KP = sm + 2 * 128 * QSTR;

    int bh = blockIdx.z, b = bh >> 3, h = bh & 7;
    int bi = blockIdx.y * 128, bj = blockIdx.x * 128;
    int tid = threadIdx.x, warp = tid >> 5, lane = tid & 31;
    int gid = lane >> 2, tig = lane & 3;
    int wm = warp & 1, wn = warp >> 1;
    size_t obase = (size_t)bh * T * T;

    #pragma unroll
    for (int l = 0; l < 8; l++) {
        int idx = tid + l * 256;
        int row = idx >> 4, c4 = (idx & 15) * 4;
        cp16(&KP[row * QSTR + c4], &k[(size_t)((b * T + bj + row) * H + h) * DK + c4]);
    }
    cp_commit();

    #pragma unroll
    for (int l = 0; l < 8; l++) {
        int idx = tid + l * 256;
        int row = idx >> 4, c4 = (idx & 15) * 4;
        float4 vq = *(const float4*)&q[(size_t)((b * T + bi + row) * H + h) * DK + c4];
        float4 uu = *(const float4*)&ub[h * DK + c4];
        float4 vv = *(const float4*)&vb[h * DK + c4];
        Qu[row * QSTR + c4 + 0] = f2tf32(vq.x + uu.x);
        Qu[row * QSTR + c4 + 1] = f2tf32(vq.y + uu.y);
        Qu[row * QSTR + c4 + 2] = f2tf32(vq.z + uu.z);
        Qu[row * QSTR + c4 + 3] = f2tf32(vq.w + uu.w);
        Qv[row * QSTR + c4 + 0] = f2tf32(vq.x + vv.x);
        Qv[row * QSTR + c4 + 1] = f2tf32(vq.y + vv.y);
        Qv[row * QSTR + c4 + 2] = f2tf32(vq.z + vv.z);
        Qv[row * QSTR + c4 + 3] = f2tf32(vq.w + vv.w);
    }
    cp_wait0();
    __syncthreads();

    score_mma_store(Qu, KP, cs, obase, bi, bj, wm, wn, gid, tig);
    __syncthreads();

    #pragma unroll
    for (int l = 0; l < 8; l++) {
        int idx = tid + l * 256;
        int row = idx >> 4, c4 = (idx & 15) * 4;
        cp16(&KP[row * QSTR + c4], &p[(size_t)((b * T + bj + row) * H + h) * DK + c4]);
    }
    cp_commit();
    cp_wait0();
    __syncthreads();

    score_mma_store(Qv, KP, ps, obase, bi, bj, wm, wn, gid, tig);
}

// ---------------------------------------------------------------------------
// Fused rel-shift + softmax. bf16 in, tf32-rounded fp32 out.
//   shifted[i,j] = (j<=i) ? ps[i, T+j-i-1] : (j==i+1) ? 0 : ps[i+1, j-i-2]
// ---------------------------------------------------------------------------
__global__ __launch_bounds__(256) void softmax_shift_kernel(
    const __nv_bfloat16* __restrict__ cs, const __nv_bfloat16* __restrict__ ps,
    float* __restrict__ attn)
{
    int i  = blockIdx.x;
    int bh = blockIdx.y;
    int tid = threadIdx.x;
    size_t base = (size_t)bh * T * T;

    float vals[4];
    float mx = -3.4e38f;
    #pragma unroll
    for (int l = 0; l < 4; l++) {
        int j = tid + l * 256;
        float pv;
        if (j <= i)
            pv = __bfloat162float(ps[base + (size_t)i * T + (T + j - i - 1)]);
        else if (j == i + 1)
            pv = 0.0f;
        else
            pv = __bfloat162float(ps[base + (size_t)(i + 1) * T + (j - i - 2)]);
        float s = __bfloat162float(cs[base + (size_t)i * T + j]) + pv;
        vals[l] = s;
        mx = fmaxf(mx, s);
    }

    __shared__ float red[8];
    #pragma unroll
    for (int o = 16; o > 0; o >>= 1) mx = fmaxf(mx, __shfl_xor_sync(0xffffffffu, mx, o));
    if ((tid & 31) == 0) red[tid >> 5] = mx;
    __syncthreads();
    if (tid == 0) {
        float m = red[0];
        #pragma unroll
        for (int w = 1; w < 8; w++) m = fmaxf(m, red[w]);
        red[0] = m;
    }
    __syncthreads();
    mx = red[0];
    __syncthreads();

    float sum = 0.f;
    #pragma unroll
    for (int l = 0; l < 4; l++) { vals[l] = __expf(vals[l] - mx); sum += vals[l]; }
    #pragma unroll
    for (int o = 16; o > 0; o >>= 1) sum += __shfl_xor_sync(0xffffffffu, sum, o);
    if ((tid & 31) == 0) red[tid >> 5] = sum;
    __syncthreads();
    if (tid == 0) {
        float s = 0.f;
        #pragma unroll
        for (int w = 0; w < 8; w++) s += red[w];
        red[0] = s;
    }
    __syncthreads();
    float rinv = 1.0f / red[0];
    #pragma unroll
    for (int l = 0; l < 4; l++) {
        int j = tid + l * 256;
        attn[base + (size_t)i * T + j] = f2tf32(vals[l] * rinv);
    }
}

// ---------------------------------------------------------------------------
// Context: ctx[b,i,h,d] = sum_j attn[bh,i,j] * v[b,j,h,d]
// Block 128i x 64d, 256 thr (8 warps 4x2), K-step 16, 3-stage cp.async.
// attn/v are pre-rounded -> truncating loads are exact.
// ---------------------------------------------------------------------------
__global__ __launch_bounds__(256, 2) void context_tc(
    const float* __restrict__ attn, const float* __restrict__ v,
    float* __restrict__ ctx)
{
    __shared__ float As[3][128][20];
    __shared__ float Bs[3][16][72];
    int bh = blockIdx.y, b = bh >> 3, h = bh & 7;
    int bm = blockIdx.x * 128;
    int tid = threadIdx.x, warp = tid >> 5, lane = tid & 31;
    int gid = lane >> 2, tig = lane & 3;
    int wm = warp >> 1, wn = warp & 1;
    int ar = tid >> 2, ac = (tid & 3) * 4;
    int br = tid >> 4, bc = (tid & 15) * 4;
    size_t abase = (size_t)bh * T * T;

    const float* Abase = attn + abase + (size_t)(bm + ar) * T + ac;
    const float* Vbase = v + (size_t)((b * T + br) * H + h) * DK + bc;
    const int nsteps = T / 16;

    #pragma unroll
    for (int s = 0; s < 2; s++) {
        int k0 = s * 16;
        cp16(&As[s][ar][ac],      Abase + k0);
        cp16(&As[s][ar + 64][ac], Abase + (size_t)64 * T + k0);
        cp16(&Bs[s][br][bc],      Vbase + (size_t)k0 * H * DK);
        cp_commit();
    }

    float acc[2][4][4] = {};
    for (int s = 0; s < nsteps; s++) {
        cp_wait1();
        __syncthreads();
        int st = s % 3;
        if (s + 2 < nsteps) {
            int k0 = (s + 2) * 16, st2 = (s + 2) % 3;
            cp16(&As[st2][ar][ac],      Abase + k0);
            cp16(&As[st2][ar + 64][ac], Abase + (size_t)64 * T + k0);
            cp16(&Bs[st2][br][bc],      Vbase + (size_t)k0 * H * DK);
        }
        cp_commit();

        #pragma unroll
        for (int k8 = 0; k8 < 2; k8++) {
            int kb = k8 * 8;
            float af[2][4], bf[4][2];
            #pragma unroll
            for (int mt = 0; mt < 2; mt++) {
                int r = wm * 32 + mt * 16 + gid;
                af[mt][0] = As[st][r][kb + tig];
                af[mt][1] = As[st][r + 8][kb + tig];
                af[mt][2] = As[st][r][kb + tig + 4];
                af[mt][3] = As[st][r + 8][kb + tig + 4];
            }
            #pragma unroll
            for (int nt = 0; nt < 4; nt++) {
                int c = wn * 32 + nt * 8 + gid;
                bf[nt][0] = Bs[st][kb + tig][c];
                bf[nt][1] = Bs[st][kb + tig + 4][c];
            }
            #pragma unroll
            for (int mt = 0; mt < 2; mt++)
                #pragma unroll
                for (int nt = 0; nt < 4; nt++)
                    mma_tf32(acc[mt][nt], af[mt], bf[nt]);
        }
    }

    #pragma unroll
    for (int mt = 0; mt < 2; mt++) {
        int r0 = bm + wm * 32 + mt * 16 + gid;
        #pragma unroll
        for (int nt = 0; nt < 4; nt++) {
            int c0 = wn * 32 + nt * 8 + 2 * tig;
            ctx[(size_t)((b * T + r0) * H + h) * DK + c0]         = acc[mt][nt][0];
            ctx[(size_t)((b * T + r0) * H + h) * DK + c0 + 1]     = acc[mt][nt][1];
            ctx[(size_t)((b * T + r0 + 8) * H + h) * DK + c0]     = acc[mt][nt][2];
            ctx[(size_t)((b * T + r0 + 8) * H + h) * DK + c0 + 1] = acc[mt][nt][3];
        }
    }
}

// ---------------------------------------------------------------------------
extern "C" void kernel_launch(void* const* d_in, const int* in_sizes, int n_in,
                              void* d_out, int out_size)
{
    const float* query = (const float*)d_in[0];
    const float* key   = (const float*)d_in[1];
    const float* value = (const float*)d_in[2];
    const float* pos   = (const float*)d_in[3];
    const float* Wq = (const float*)d_in[4];
    const float* bq = (const float*)d_in[5];
    const float* Wk = (const float*)d_in[6];
    const float* bk = (const float*)d_in[7];
    const float* Wv = (const float*)d_in[8];
    const float* bv = (const float*)d_in[9];
    const float* Wp = (const float*)d_in[10];
    const float* ub = (const float*)d_in[11];
    const float* vb = (const float*)d_in[12];
    const float* Wo = (const float*)d_in[13];
    const float* bo = (const float*)d_in[14];
    float* out = (float*)d_out;

    float *q, *k, *v, *p, *attn, *ctx;
    __nv_bfloat16 *cs, *ps;
    cudaGetSymbolAddress((void**)&q,    g_q);
    cudaGetSymbolAddress((void**)&k,    g_k);
    cudaGetSymbolAddress((void**)&v,    g_v);
    cudaGetSymbolAddress((void**)&p,    g_p);
    cudaGetSymbolAddress((void**)&cs,   g_cs);
    cudaGetSymbolAddress((void**)&ps,   g_ps);
    cudaGetSymbolAddress((void**)&attn, g_attn);
    cudaGetSymbolAddress((void**)&ctx,  g_ctx);

    const int SMEM_SCORE = 3 * 128 * QSTR * 4;   // 104448 B
    cudaFuncSetAttribute(score_fused,
        cudaFuncAttributeMaxDynamicSharedMemorySize, SMEM_SCORE);

    dim3 gproj(D / 128, BT / 128);          // (4, 64)
    sgemm_bias_tc<<<gproj, 256>>>(query, Wq, bq, q, BT, D, D, 1);
    sgemm_bias_tc<<<gproj, 256>>>(key,   Wk, bk, k, BT, D, D, 1);
    sgemm_bias_tc<<<gproj, 256>>>(value, Wv, bv, v, BT, D, D, 1);
    sgemm_bias_tc<<<gproj, 256>>>(pos,   Wp, nullptr, p, BT, D, D, 1);

    dim3 gsc(T / 128, T / 128, B * H);      // (8, 8, 64)
    score_fused<<<gsc, 256, SMEM_SCORE>>>(q, k, p, ub, vb, cs, ps);

    dim3 gsm(T, B * H);                     // (1024, 64)
    softmax_shift_kernel<<<gsm, 256>>>(cs, ps, attn);

    dim3 gctx(T / 128, B * H);              // (8, 64)
    context_tc<<<gctx, 256>>>(attn, v, ctx);

    sgemm_bias_tc<<<gproj, 256>>>(ctx, Wo, bo, out, BT, D, D, 0);
}

// round 9
// speedup vs baseline: 2.5302x; 1.4979x over previous
#include <cuda_runtime.h>
#include <cuda_fp16.h>
#include <cuda_bf16.h>

#define B 8
#define T 1024
#define D 512
#define H 8
#define DK 64
#define BT (B*T)   // 8192

__device__ __half g_q16[BT * D];
__device__ __half g_k16[BT * D];
__device__ __half g_v16[BT * D];
__device__ __half g_p16[BT * D];
__device__ __half g_v16i[BT * D];            // [bh][t/2][d] k-paired half2 words
__device__ __nv_bfloat16 g_cs[(size_t)B * H * T * T];
__device__ __nv_bfloat16 g_ps[(size_t)B * H * T * T];
__device__ __half g_attn16[(size_t)B * H * T * T];
__device__ __half g_ctx16[BT * D];

__device__ __forceinline__ unsigned packh2(float lo, float hi) {
    __half2 h = __floats2half2_rn(lo, hi);
    return *(unsigned*)&h;
}
__device__ __forceinline__ float2 unpackh2(unsigned u) {
    __half2 h = *(__half2*)&u;
    return __half22float2(h);
}

// mma.sync m16n8k16 f16 row.col, fp32 accumulate
__device__ __forceinline__ void mma_f16(float* c, unsigned a0, unsigned a1,
                                        unsigned a2, unsigned a3,
                                        unsigned b0, unsigned b1) {
    asm volatile(
        "mma.sync.aligned.m16n8k16.row.col.f32.f16.f16.f32 "
        "{%0,%1,%2,%3}, {%4,%5,%6,%7}, {%8,%9}, {%0,%1,%2,%3};"
        : "+f"(c[0]), "+f"(c[1]), "+f"(c[2]), "+f"(c[3])
        : "r"(a0), "r"(a1), "r"(a2), "r"(a3), "r"(b0), "r"(b1));
}

__device__ __forceinline__ void cp16g(void* dst, const void* src) {
    unsigned d = (unsigned)__cvta_generic_to_shared(dst);
    asm volatile("cp.async.ca.shared.global [%0], [%1], 16;" :: "r"(d), "l"(src));
}
__device__ __forceinline__ void cp_commit() { asm volatile("cp.async.commit_group;"); }
__device__ __forceinline__ void cp_wait1()  { asm volatile("cp.async.wait_group 1;"); }
__device__ __forceinline__ void cp_wait0()  { asm volatile("cp.async.wait_group 0;"); }

// ---------------------------------------------------------------------------
// GEMM (fp16 MMA): C = A[M,K]@W[K,N] + bias.  A fp32 or fp16, C fp16 or fp32.
// Block 128x128, 256 thr (8 warps 2x4), warp 64x32, K-step 16, reg-staged 2-buf.
// M=BT, N=K=D.
// ---------------------------------------------------------------------------
__global__ __launch_bounds__(256) void gemm_h(
    const float* __restrict__ Af, const __half* __restrict__ Ah,
    const float* __restrict__ W, const float* __restrict__ bias,
    float* __restrict__ Cf, __half* __restrict__ Ch)
{
    const int N = D, K = D;
    __shared__ unsigned As[2][128 * 12];   // [row][8 k-pair words + 4 pad]
    __shared__ unsigned Ws[2][8 * 136];    // [kkpair][128 n words + 8 pad]

    int tid = threadIdx.x, warp = tid >> 5, lane = tid & 31;
    int gid = lane >> 2, tig = lane & 3;
    int wm = warp & 1, wn = warp >> 1;
    int bm = blockIdx.y * 128, bn = blockIdx.x * 128;

    int arow = tid >> 1, aoff = (tid & 1) * 8;     // 8 k per thread
    int wkk = tid >> 5, wc4 = (tid & 31) * 4;      // W: k rows 2kk,2kk+1, 4 n

    const float* Afp = Af ? Af + (size_t)(bm + arow) * K + aoff : nullptr;
    const __half* Ahp = Ah ? Ah + (size_t)(bm + arow) * K + aoff : nullptr;
    const float* Wp0 = W + (size_t)(2 * wkk) * N + bn + wc4;
    const float* Wp1 = Wp0 + N;

    float4 fa0, fa1; uint4 ha;
    if (Af) { fa0 = *(const float4*)Afp; fa1 = *(const float4*)(Afp + 4); }
    else    { ha = *(const uint4*)Ahp; }
    float4 w0 = *(const float4*)Wp0;
    float4 w1 = *(const float4*)Wp1;

    float acc[4][4][4] = {};
    const int nsteps = K / 16;
    for (int s = 0; s < nsteps; s++) {
        int buf = s & 1;
        unsigned* ad = &As[buf][arow * 12 + aoff / 2];
        if (Af) {
            ad[0] = packh2(fa0.x, fa0.y); ad[1] = packh2(fa0.z, fa0.w);
            ad[2] = packh2(fa1.x, fa1.y); ad[3] = packh2(fa1.z, fa1.w);
        } else {
            ad[0] = ha.x; ad[1] = ha.y; ad[2] = ha.z; ad[3] = ha.w;
        }
        unsigned* wd = &Ws[buf][wkk * 136 + wc4];
        wd[0] = packh2(w0.x, w1.x); wd[1] = packh2(w0.y, w1.y);
        wd[2] = packh2(w0.z, w1.z); wd[3] = packh2(w0.w, w1.w);
        __syncthreads();

        if (s + 1 < nsteps) {
            int k0 = (s + 1) * 16;
            if (Af) {
                fa0 = *(const float4*)(Afp + k0);
                fa1 = *(const float4*)(Afp + k0 + 4);
            } else {
                ha = *(const uint4*)(Ahp + k0);
            }
            w0 = *(const float4*)(Wp0 + (size_t)k0 * N);
            w1 = *(const float4*)(Wp1 + (size_t)k0 * N);
        }

        unsigned af[4][4], bf[4][2];
        #pragma unroll
        for (int mt = 0; mt < 4; mt++) {
            int r = wm * 64 + mt * 16 + gid;
            af[mt][0] = As[buf][r * 12 + tig];
            af[mt][1] = As[buf][(r + 8) * 12 + tig];
            af[mt][2] = As[buf][r * 12 + 4 + tig];
            af[mt][3] = As[buf][(r + 8) * 12 + 4 + tig];
        }
        #pragma unroll
        for (int nt = 0; nt < 4; nt++) {
            int c = wn * 32 + nt * 8 + gid;
            bf[nt][0] = Ws[buf][tig * 136 + c];
            bf[nt][1] = Ws[buf][(tig + 4) * 136 + c];
        }
        #pragma unroll
        for (int mt = 0; mt < 4; mt++)
            #pragma unroll
            for (int nt = 0; nt < 4; nt++)
                mma_f16(acc[mt][nt], af[mt][0], af[mt][1], af[mt][2], af[mt][3],
                        bf[nt][0], bf[nt][1]);
        __syncthreads();
    }

    #pragma unroll
    for (int mt = 0; mt < 4; mt++) {
        int r0 = bm + wm * 64 + mt * 16 + gid;
        #pragma unroll
        for (int nt = 0; nt < 4; nt++) {
            int c0 = bn + wn * 32 + nt * 8 + 2 * tig;
            float b0 = bias ? bias[c0] : 0.f;
            float b1 = bias ? bias[c0 + 1] : 0.f;
            float v0 = acc[mt][nt][0] + b0, v1 = acc[mt][nt][1] + b1;
            float v2 = acc[mt][nt][2] + b0, v3 = acc[mt][nt][3] + b1;
            if (Ch) {
                *(unsigned*)&Ch[(size_t)r0 * N + c0]       = packh2(v0, v1);
                *(unsigned*)&Ch[(size_t)(r0 + 8) * N + c0] = packh2(v2, v3);
            } else {
                Cf[(size_t)r0 * N + c0]           = v0;
                Cf[(size_t)r0 * N + c0 + 1]       = v1;
                Cf[(size_t)(r0 + 8) * N + c0]     = v2;
                Cf[(size_t)(r0 + 8) * N + c0 + 1] = v3;
            }
        }
    }
}

// ---------------------------------------------------------------------------
// V reshuffle: v16 [b][t][h][d] -> v16i [bh][t/2][d] k-paired half2 words.
// ---------------------------------------------------------------------------
__global__ __launch_bounds__(256) void v_reshape(
    const __half* __restrict__ v16, __half* __restrict__ v16i)
{
    int gidx = blockIdx.x * 256 + threadIdx.x;   // 262144
    int d8 = gidx & 7;
    int rem = gidx >> 3;
    int kk = rem & 511;
    int bh = rem >> 9;
    int b = bh >> 3, h = bh & 7;

    uint4 x = *(const uint4*)(v16 + ((size_t)(b * T + 2 * kk) * H + h) * DK + d8 * 8);
    uint4 y = *(const uint4*)(v16 + ((size_t)(b * T + 2 * kk + 1) * H + h) * DK + d8 * 8);
    const unsigned short* xs = (const unsigned short*)&x;
    const unsigned short* ys = (const unsigned short*)&y;
    unsigned out[8];
    #pragma unroll
    for (int i = 0; i < 8; i++)
        out[i] = (unsigned)xs[i] | ((unsigned)ys[i] << 16);
    unsigned* dst = (unsigned*)v16i + ((size_t)bh * 512 + kk) * 64 + d8 * 8;
    *(uint4*)(dst + 0) = *(uint4*)(out + 0);
    *(uint4*)(dst + 4) = *(uint4*)(out + 4);
}

// ---------------------------------------------------------------------------
// Fused scores (fp16): cs = scale*(q+u)·k, ps = scale*(q+v)·p -> bf16.
// Block 128x128, 256 thr (8 warps 2x4), warp 64x32, K=64 (4 k16 steps).
// ---------------------------------------------------------------------------
#define QS 36
__device__ __forceinline__ void score_mma_bf16(
    const unsigned* __restrict__ Q, const unsigned* __restrict__ KP,
    __nv_bfloat16* __restrict__ out, size_t obase, int bi, int bj,
    int wm, int wn, int gid, int tig)
{
    float acc[4][4][4] = {};
    #pragma unroll
    for (int ks = 0; ks < 4; ks++) {
        unsigned af[4][4], bf[4][2];
        #pragma unroll
        for (int mt = 0; mt < 4; mt++) {
            int r = wm * 64 + mt * 16 + gid;
            af[mt][0] = Q[r * QS + ks * 8 + tig];
            af[mt][1] = Q[(r + 8) * QS + ks * 8 + tig];
            af[mt][2] = Q[r * QS + ks * 8 + 4 + tig];
            af[mt][3] = Q[(r + 8) * QS + ks * 8 + 4 + tig];
        }
        #pragma unroll
        for (int nt = 0; nt < 4; nt++) {
            int c = wn * 32 + nt * 8 + gid;
            bf[nt][0] = KP[c * QS + ks * 8 + tig];
            bf[nt][1] = KP[c * QS + ks * 8 + 4 + tig];
        }
        #pragma unroll
        for (int mt = 0; mt < 4; mt++)
            #pragma unroll
            for (int nt = 0; nt < 4; nt++)
                mma_f16(acc[mt][nt], af[mt][0], af[mt][1], af[mt][2], af[mt][3],
                        bf[nt][0], bf[nt][1]);
    }
    const float scale = 0.04419417382415922f;   // 1/sqrt(512)
    #pragma unroll
    for (int mt = 0; mt < 4; mt++) {
        int r0 = bi + wm * 64 + mt * 16 + gid;
        #pragma unroll
        for (int nt = 0; nt < 4; nt++) {
            int c0 = bj + wn * 32 + nt * 8 + 2 * tig;
            __nv_bfloat162 p0 = __floats2bfloat162_rn(acc[mt][nt][0] * scale,
                                                      acc[mt][nt][1] * scale);
            __nv_bfloat162 p1 = __floats2bfloat162_rn(acc[mt][nt][2] * scale,
                                                      acc[mt][nt][3] * scale);
            *(__nv_bfloat162*)&out[obase + (size_t)r0 * T + c0]       = p0;
            *(__nv_bfloat162*)&out[obase + (size_t)(r0 + 8) * T + c0] = p1;
        }
    }
}

__global__ __launch_bounds__(256) void score_fused_f16(
    const __half* __restrict__ q16, const __half* __restrict__ k16,
    const __half* __restrict__ p16, const float* __restrict__ ub,
    const float* __restrict__ vb,
    __nv_bfloat16* __restrict__ cs, __nv_bfloat16* __restrict__ ps)
{
    extern __shared__ unsigned sm[];
    unsigned* Qu = sm;
    unsigned* Qv = sm + 128 * QS;
    unsigned* KP = sm + 2 * 128 * QS;
    __shared__ float sub[DK], svb[DK];

    int bh = blockIdx.z, b = bh >> 3, h = bh & 7;
    int bi = blockIdx.y * 128, bj = blockIdx.x * 128;
    int tid = threadIdx.x, warp = tid >> 5, lane = tid & 31;
    int gid = lane >> 2, tig = lane & 3;
    int wm = warp & 1, wn = warp >> 1;
    size_t obase = (size_t)bh * T * T;

    if (tid < DK) {
        sub[tid] = ub[h * DK + tid];
        svb[tid] = vb[h * DK + tid];
    }

    // async K tile: 128 rows x 64 halves (8 x 16B per row)
    #pragma unroll
    for (int l = 0; l < 4; l++) {
        int idx = tid + l * 256;
        int row = idx >> 3, c16 = idx & 7;
        cp16g((char*)KP + row * (QS * 4) + c16 * 16,
              k16 + ((size_t)(b * T + bj + row) * H + h) * DK + c16 * 8);
    }
    cp_commit();
    __syncthreads();   // sub/svb visible

    // Q staging with bias add: row = tid>>1, 32 halves at (tid&1)*32
    {
        int row = tid >> 1, doff = (tid & 1) * 32;
        const uint4* qp = (const uint4*)(q16 + ((size_t)(b * T + bi + row) * H + h) * DK + doff);
        uint4 r4[4] = { qp[0], qp[1], qp[2], qp[3] };
        const unsigned* rw = (const unsigned*)r4;
        unsigned* qud = &Qu[row * QS + doff / 2];
        unsigned* qvd = &Qv[row * QS + doff / 2];
        #pragma unroll
        for (int u = 0; u < 16; u++) {
            float2 f = unpackh2(rw[u]);
            int d = doff + 2 * u;
            qud[u] = packh2(f.x + sub[d], f.y + sub[d + 1]);
            qvd[u] = packh2(f.x + svb[d], f.y + svb[d + 1]);
        }
    }
    cp_wait0();
    __syncthreads();

    score_mma_bf16(Qu, KP, cs, obase, bi, bj, wm, wn, gid, tig);
    __syncthreads();

    #pragma unroll
    for (int l = 0; l < 4; l++) {
        int idx = tid + l * 256;
        int row = idx >> 3, c16 = idx & 7;
        cp16g((char*)KP + row * (QS * 4) + c16 * 16,
              p16 + ((size_t)(b * T + bj + row) * H + h) * DK + c16 * 8);
    }
    cp_commit();
    cp_wait0();
    __syncthreads();

    score_mma_bf16(Qv, KP, ps, obase, bi, bj, wm, wn, gid, tig);
}

// ---------------------------------------------------------------------------
// Fused rel-shift + softmax: bf16 in, fp16 attn out. 4 consecutive j/thread.
// ---------------------------------------------------------------------------
__device__ __forceinline__ float bf2f(unsigned short u) {
    return __uint_as_float(((unsigned)u) << 16);
}

__global__ __launch_bounds__(256) void softmax_shift_kernel(
    const __nv_bfloat16* __restrict__ cs, const __nv_bfloat16* __restrict__ ps,
    __half* __restrict__ attn)
{
    int i  = blockIdx.x;
    int bh = blockIdx.y;
    int tid = threadIdx.x;
    size_t base = (size_t)bh * T * T;
    int j0 = tid * 4;

    ushort4 craw = *(const ushort4*)&cs[base + (size_t)i * T + j0];
    const unsigned short* cw = (const unsigned short*)&craw;

    float vals[4];
    float mx = -3.4e38f;
    #pragma unroll
    for (int l = 0; l < 4; l++) {
        int j = j0 + l;
        float pv;
        if (j <= i)
            pv = bf2f(*(const unsigned short*)&ps[base + (size_t)i * T + (T + j - i - 1)]);
        else if (j == i + 1)
            pv = 0.0f;
        else
            pv = bf2f(*(const unsigned short*)&ps[base + (size_t)(i + 1) * T + (j - i - 2)]);
        float s = bf2f(cw[l]) + pv;
        vals[l] = s;
        mx = fmaxf(mx, s);
    }

    __shared__ float red[8];
    #pragma unroll
    for (int o = 16; o > 0; o >>= 1) mx = fmaxf(mx, __shfl_xor_sync(0xffffffffu, mx, o));
    if ((tid & 31) == 0) red[tid >> 5] = mx;
    __syncthreads();
    if (tid == 0) {
        float m = red[0];
        #pragma unroll
        for (int w = 1; w < 8; w++) m = fmaxf(m, red[w]);
        red[0] = m;
    }
    __syncthreads();
    mx = red[0];
    __syncthreads();

    float sum = 0.f;
    #pragma unroll
    for (int l = 0; l < 4; l++) { vals[l] = __expf(vals[l] - mx); sum += vals[l]; }
    #pragma unroll
    for (int o = 16; o > 0; o >>= 1) sum += __shfl_xor_sync(0xffffffffu, sum, o);
    if ((tid & 31) == 0) red[tid >> 5] = sum;
    __syncthreads();
    if (tid == 0) {
        float s = 0.f;
        #pragma unroll
        for (int w = 0; w < 8; w++) s += red[w];
        red[0] = s;
    }
    __syncthreads();
    float rinv = 1.0f / red[0];
    uint2 outp;
    outp.x = packh2(vals[0] * rinv, vals[1] * rinv);
    outp.y = packh2(vals[2] * rinv, vals[3] * rinv);
    *(uint2*)&attn[base + (size_t)i * T + j0] = outp;
}

// ---------------------------------------------------------------------------
// Context (fp16): ctx16[b,i,h,d] = sum_j attn[bh,i,j] * v[b,j,h,d]
// Block 128i x 64d, 256 thr (8 warps 4x2), warp 32x32, K-step 32 j, 3-stage cp.
// ---------------------------------------------------------------------------
__global__ __launch_bounds__(256, 2) void context_f16(
    const __half* __restrict__ attn, const __half* __restrict__ v16i,
    __half* __restrict__ ctx16)
{
    __shared__ unsigned As[3][128 * 20];   // [row][16 k-pair words + 4 pad]
    __shared__ unsigned Vs[3][16 * 72];    // [kkpair][64 d words + 8 pad]
    int bh = blockIdx.y, b = bh >> 3, h = bh & 7;
    int bm = blockIdx.x * 128;
    int tid = threadIdx.x, warp = tid >> 5, lane = tid & 31;
    int gid = lane >> 2, tig = lane & 3;
    int wm = warp >> 1, wn = warp & 1;
    size_t abase = (size_t)bh * T * T;
    const unsigned* vsrc = (const unsigned*)v16i + (size_t)bh * 512 * 64;

    const int nsteps = T / 32;   // 32

    #pragma unroll
    for (int s = 0; s < 2; s++) {
        int k0 = s * 32;
        #pragma unroll
        for (int l = 0; l < 2; l++) {
            int idx = tid + l * 256;
            int row = idx >> 2, c = idx & 3;
            cp16g((char*)As[s] + row * 80 + c * 16,
                  attn + abase + (size_t)(bm + row) * T + k0 + c * 8);
        }
        {
            int kk = tid >> 4, c = tid & 15;
            cp16g((char*)Vs[s] + kk * 288 + c * 16,
                  vsrc + (size_t)(k0 / 2 + kk) * 64 + c * 4);
        }
        cp_commit();
    }

    float acc[2][4][4] = {};
    for (int s = 0; s < nsteps; s++) {
        cp_wait1();
        __syncthreads();
        int st = s % 3;
        if (s + 2 < nsteps) {
            int k0 = (s + 2) * 32, st2 = (s + 2) % 3;
            #pragma unroll
            for (int l = 0; l < 2; l++) {
                int idx = tid + l * 256;
                int row = idx >> 2, c = idx & 3;
                cp16g((char*)As[st2] + row * 80 + c * 16,
                      attn + abase + (size_t)(bm + row) * T + k0 + c * 8);
            }
            int kk = tid >> 4, c = tid & 15;
            cp16g((char*)Vs[st2] + kk * 288 + c * 16,
                  vsrc + (size_t)(k0 / 2 + kk) * 64 + c * 4);
        }
        cp_commit();

        #pragma unroll
        for (int ks = 0; ks < 2; ks++) {
            unsigned af[2][4], bf[4][2];
            #pragma unroll
            for (int mt = 0; mt < 2; mt++) {
                int r = wm * 32 + mt * 16 + gid;
                af[mt][0] = As[st][r * 20 + ks * 8 + tig];
                af[mt][1] = As[st][(r + 8) * 20 + ks * 8 + tig];
                af[mt][2] = As[st][r * 20 + ks * 8 + 4 + tig];
                af[mt][3] = As[st][(r + 8) * 20 + ks * 8 + 4 + tig];
            }
            #pragma unroll
            for (int nt = 0; nt < 4; nt++) {
                int c = wn * 32 + nt * 8 + gid;
                bf[nt][0] = Vs[st][(ks * 8 + tig) * 72 + c];
                bf[nt][1] = Vs[st][(ks * 8 + 4 + tig) * 72 + c];
            }
            #pragma unroll
            for (int mt = 0; mt < 2; mt++)
                #pragma unroll
                for (int nt = 0; nt < 4; nt++)
                    mma_f16(acc[mt][nt], af[mt][0], af[mt][1], af[mt][2], af[mt][3],
                            bf[nt][0], bf[nt][1]);
        }
    }

    #pragma unroll
    for (int mt = 0; mt < 2; mt++) {
        int r0 = bm + wm * 32 + mt * 16 + gid;
        #pragma unroll
        for (int nt = 0; nt < 4; nt++) {
            int c0 = wn * 32 + nt * 8 + 2 * tig;
            *(unsigned*)&ctx16[((size_t)(b * T + r0) * H + h) * DK + c0] =
                packh2(acc[mt][nt][0], acc[mt][nt][1]);
            *(unsigned*)&ctx16[((size_t)(b * T + r0 + 8) * H + h) * DK + c0] =
                packh2(acc[mt][nt][2], acc[mt][nt][3]);
        }
    }
}

// ---------------------------------------------------------------------------
extern "C" void kernel_launch(void* const* d_in, const int* in_sizes, int n_in,
                              void* d_out, int out_size)
{
    const float* query = (const float*)d_in[0];
    const float* key   = (const float*)d_in[1];
    const float* value = (const float*)d_in[2];
    const float* pos   = (const float*)d_in[3];
    const float* Wq = (const float*)d_in[4];
    const float* bq = (const float*)d_in[5];
    const float* Wk = (const float*)d_in[6];
    const float* bk = (const float*)d_in[7];
    const float* Wv = (const float*)d_in[8];
    const float* bv = (const float*)d_in[9];
    const float* Wp = (const float*)d_in[10];
    const float* ub = (const float*)d_in[11];
    const float* vb = (const float*)d_in[12];
    const float* Wo = (const float*)d_in[13];
    const float* bo = (const float*)d_in[14];
    float* out = (float*)d_out;

    __half *q16, *k16, *v16, *p16, *v16i, *attn16, *ctx16;
    __nv_bfloat16 *cs, *ps;
    cudaGetSymbolAddress((void**)&q16,    g_q16);
    cudaGetSymbolAddress((void**)&k16,    g_k16);
    cudaGetSymbolAddress((void**)&v16,    g_v16);
    cudaGetSymbolAddress((void**)&p16,    g_p16);
    cudaGetSymbolAddress((void**)&v16i,   g_v16i);
    cudaGetSymbolAddress((void**)&cs,     g_cs);
    cudaGetSymbolAddress((void**)&ps,     g_ps);
    cudaGetSymbolAddress((void**)&attn16, g_attn16);
    cudaGetSymbolAddress((void**)&ctx16,  g_ctx16);

    const int SMEM_SCORE = 3 * 128 * QS * 4;   // 55296 B
    cudaFuncSetAttribute(score_fused_f16,
        cudaFuncAttributeMaxDynamicSharedMemorySize, SMEM_SCORE);

    dim3 gproj(D / 128, BT / 128);          // (4, 64)
    gemm_h<<<gproj, 256>>>(query, nullptr, Wq, bq, nullptr, q16);
    gemm_h<<<gproj, 256>>>(key,   nullptr, Wk, bk, nullptr, k16);
    gemm_h<<<gproj, 256>>>(value, nullptr, Wv, bv, nullptr, v16);
    gemm_h<<<gproj, 256>>>(pos,   nullptr, Wp, nullptr, nullptr, p16);

    v_reshape<<<1024, 256>>>(v16, v16i);

    dim3 gsc(T / 128, T / 128, B * H);      // (8, 8, 64)
    score_fused_f16<<<gsc, 256, SMEM_SCORE>>>(q16, k16, p16, ub, vb, cs, ps);

    dim3 gsm(T, B * H);                     // (1024, 64)
    softmax_shift_kernel<<<gsm, 256>>>(cs, ps, attn16);

    dim3 gctx(T / 128, B * H);              // (8, 64)
    context_f16<<<gctx, 256>>>(attn16, v16i, ctx16);

    gemm_h<<<gproj, 256>>>(nullptr, ctx16, Wo, bo, out, nullptr);
}

// round 10
// speedup vs baseline: 2.7507x; 1.0872x over previous
#include <cuda_runtime.h>
#include <cuda_fp16.h>
#include <cuda_bf16.h>

#define B 8
#define T 1024
#define D 512
#define H 8
#define DK 64
#define BT (B*T)   // 8192

// Scratch (static device globals — no runtime allocation)
__device__ __half g_x16[4][BT * D];          // fp16 copies of query/key/value/pos
__device__ unsigned g_w16[5][D * D / 2];     // k-paired half2 weights
__device__ __half g_q16[BT * D];
__device__ __half g_k16[BT * D];
__device__ __half g_v16[BT * D];
__device__ __half g_p16[BT * D];
__device__ __half g_v16i[BT * D];            // [bh][t/2][d] k-paired half2 words
__device__ __nv_bfloat16 g_cs[(size_t)B * H * T * T];
__device__ __nv_bfloat16 g_ps[(size_t)B * H * T * T];
__device__ __half g_attn16[(size_t)B * H * T * T];
__device__ __half g_ctx16[BT * D];

__device__ __forceinline__ unsigned packh2(float lo, float hi) {
    __half2 h = __floats2half2_rn(lo, hi);
    return *(unsigned*)&h;
}
__device__ __forceinline__ float2 unpackh2(unsigned u) {
    __half2 h = *(__half2*)&u;
    return __half22float2(h);
}

// mma.sync m16n8k16 f16 row.col, fp32 accumulate
__device__ __forceinline__ void mma_f16(float* c, unsigned a0, unsigned a1,
                                        unsigned a2, unsigned a3,
                                        unsigned b0, unsigned b1) {
    asm volatile(
        "mma.sync.aligned.m16n8k16.row.col.f32.f16.f16.f32 "
        "{%0,%1,%2,%3}, {%4,%5,%6,%7}, {%8,%9}, {%0,%1,%2,%3};"
        : "+f"(c[0]), "+f"(c[1]), "+f"(c[2]), "+f"(c[3])
        : "r"(a0), "r"(a1), "r"(a2), "r"(a3), "r"(b0), "r"(b1));
}

__device__ __forceinline__ void cp16g(void* dst, const void* src) {
    unsigned d = (unsigned)__cvta_generic_to_shared(dst);
    asm volatile("cp.async.ca.shared.global [%0], [%1], 16;" :: "r"(d), "l"(src));
}
__device__ __forceinline__ void cp_commit() { asm volatile("cp.async.commit_group;"); }
__device__ __forceinline__ void cp_wait1()  { asm volatile("cp.async.wait_group 1;"); }
__device__ __forceinline__ void cp_wait0()  { asm volatile("cp.async.wait_group 0;"); }

// ---------------------------------------------------------------------------
// One-time conversions
// ---------------------------------------------------------------------------
struct ActPtrs { const float* in[4]; __half* out[4]; };

__global__ __launch_bounds__(256) void cvt_act(ActPtrs ap)
{
    int z = blockIdx.y;
    const float* in = ap.in[z];
    __half* out = ap.out[z];
    size_t i = ((size_t)blockIdx.x * 256 + threadIdx.x) * 8;
    float4 a = *(const float4*)&in[i];
    float4 b = *(const float4*)&in[i + 4];
    uint4 o;
    o.x = packh2(a.x, a.y); o.y = packh2(a.z, a.w);
    o.z = packh2(b.x, b.y); o.w = packh2(b.z, b.w);
    *(uint4*)&out[i] = o;
}

struct WPtrs { const float* in[5]; unsigned* out[5]; };

__global__ __launch_bounds__(256) void cvt_w(WPtrs wp)
{
    int z = blockIdx.y;
    const float* W = wp.in[z];
    unsigned* O = wp.out[z];
    int idx = blockIdx.x * 256 + threadIdx.x;   // 32768 = 256 kp * 128 n4
    int kp = idx >> 7, n4 = (idx & 127) * 4;
    float4 w0 = *(const float4*)&W[(size_t)(2 * kp) * D + n4];
    float4 w1 = *(const float4*)&W[(size_t)(2 * kp + 1) * D + n4];
    uint4 o;
    o.x = packh2(w0.x, w1.x); o.y = packh2(w0.y, w1.y);
    o.z = packh2(w0.z, w1.z); o.w = packh2(w0.w, w1.w);
    *(uint4*)&O[(size_t)kp * D + n4] = o;
}

// ---------------------------------------------------------------------------
// GEMM (all fp16, cp.async 3-stage): C = A[M,512]@W[512,512] + bias.
// Block 128x128, 256 thr (8 warps 2x4), warp 64x32, K-step 32, 1 sync/step.
// z-batched via GArgs; Ch!=null -> fp16 out else fp32.
// ---------------------------------------------------------------------------
struct GArgs {
    const __half* A[5];
    const unsigned* W[5];     // k-paired [K/2][N] half2 words
    const float* bias[5];
    __half* Ch[5];
    float* Cf[5];
};

__global__ __launch_bounds__(256) void gemm_h16(GArgs ga, int base)
{
    const int N = D, K = D;
    int gi = base + blockIdx.z;
    const __half* A = ga.A[gi];
    const unsigned* W = ga.W[gi];
    const float* bias = ga.bias[gi];
    __half* Ch = ga.Ch[gi];
    float* Cf = ga.Cf[gi];

    extern __shared__ unsigned sm[];
    unsigned* As = sm;                 // [3][128*20]
    unsigned* Ws = sm + 3 * 128 * 20;  // [3][16*136]

    int tid = threadIdx.x, warp = tid >> 5, lane = tid & 31;
    int gid = lane >> 2, tig = lane & 3;
    int wm = warp & 1, wn = warp >> 1;
    int bm = blockIdx.y * 128, bn = blockIdx.x * 128;

    const int nsteps = K / 32;   // 16

    // load issue helper indices
    int arow0 = tid >> 2, ac0 = tid & 3;          // l=0: rows 0..63
    int arow1 = arow0 + 64;                       // l=1
    int wkk0 = tid >> 5, wc0 = tid & 31;          // l=0: kk 0..7
    int wkk1 = wkk0 + 8;                          // l=1

    #pragma unroll
    for (int s = 0; s < 2; s++) {
        int k0 = s * 32;
        unsigned* as = As + (s % 3) * (128 * 20);
        unsigned* ws = Ws + (s % 3) * (16 * 136);
        cp16g(as + arow0 * 20 + ac0 * 4, A + (size_t)(bm + arow0) * K + k0 + ac0 * 8);
        cp16g(as + arow1 * 20 + ac0 * 4, A + (size_t)(bm + arow1) * K + k0 + ac0 * 8);
        cp16g(ws + wkk0 * 136 + wc0 * 4, W + (size_t)(k0 / 2 + wkk0) * N + bn + wc0 * 4);
        cp16g(ws + wkk1 * 136 + wc0 * 4, W + (size_t)(k0 / 2 + wkk1) * N + bn + wc0 * 4);
        cp_commit();
    }

    float acc[4][4][4] = {};
    for (int s = 0; s < nsteps; s++) {
        cp_wait1();
        __syncthreads();
        int st = s % 3;
        if (s + 2 < nsteps) {
            int k0 = (s + 2) * 32, st2 = (s + 2) % 3;
            unsigned* as = As + st2 * (128 * 20);
            unsigned* ws = Ws + st2 * (16 * 136);
            cp16g(as + arow0 * 20 + ac0 * 4, A + (size_t)(bm + arow0) * K + k0 + ac0 * 8);
            cp16g(as + arow1 * 20 + ac0 * 4, A + (size_t)(bm + arow1) * K + k0 + ac0 * 8);
            cp16g(ws + wkk0 * 136 + wc0 * 4, W + (size_t)(k0 / 2 + wkk0) * N + bn + wc0 * 4);
            cp16g(ws + wkk1 * 136 + wc0 * 4, W + (size_t)(k0 / 2 + wkk1) * N + bn + wc0 * 4);
        }
        cp_commit();

        const unsigned* as = As + st * (128 * 20);
        const unsigned* ws = Ws + st * (16 * 136);
        #pragma unroll
        for (int ks = 0; ks < 2; ks++) {
            unsigned af[4][4], bf[4][2];
            #pragma unroll
            for (int mt = 0; mt < 4; mt++) {
                int r = wm * 64 + mt * 16 + gid;
                af[mt][0] = as[r * 20 + ks * 8 + tig];
                af[mt][1] = as[(r + 8) * 20 + ks * 8 + tig];
                af[mt][2] = as[r * 20 + ks * 8 + 4 + tig];
                af[mt][3] = as[(r + 8) * 20 + ks * 8 + 4 + tig];
            }
            #pragma unroll
            for (int nt = 0; nt < 4; nt++) {
                int c = wn * 32 + nt * 8 + gid;
                bf[nt][0] = ws[(ks * 8 + tig) * 136 + c];
                bf[nt][1] = ws[(ks * 8 + 4 + tig) * 136 + c];
            }
            #pragma unroll
            for (int mt = 0; mt < 4; mt++)
                #pragma unroll
                for (int nt = 0; nt < 4; nt++)
                    mma_f16(acc[mt][nt], af[mt][0], af[mt][1], af[mt][2], af[mt][3],
                            bf[nt][0], bf[nt][1]);
        }
    }

    #pragma unroll
    for (int mt = 0; mt < 4; mt++) {
        int r0 = bm + wm * 64 + mt * 16 + gid;
        #pragma unroll
        for (int nt = 0; nt < 4; nt++) {
            int c0 = bn + wn * 32 + nt * 8 + 2 * tig;
            float b0 = bias ? bias[c0] : 0.f;
            float b1 = bias ? bias[c0 + 1] : 0.f;
            float v0 = acc[mt][nt][0] + b0, v1 = acc[mt][nt][1] + b1;
            float v2 = acc[mt][nt][2] + b0, v3 = acc[mt][nt][3] + b1;
            if (Ch) {
                *(unsigned*)&Ch[(size_t)r0 * N + c0]       = packh2(v0, v1);
                *(unsigned*)&Ch[(size_t)(r0 + 8) * N + c0] = packh2(v2, v3);
            } else {
                Cf[(size_t)r0 * N + c0]           = v0;
                Cf[(size_t)r0 * N + c0 + 1]       = v1;
                Cf[(size_t)(r0 + 8) * N + c0]     = v2;
                Cf[(size_t)(r0 + 8) * N + c0 + 1] = v3;
            }
        }
    }
}

// ---------------------------------------------------------------------------
// V reshuffle: v16 [b][t][h][d] -> v16i [bh][t/2][d] k-paired half2 words.
// ---------------------------------------------------------------------------
__global__ __launch_bounds__(256) void v_reshape(
    const __half* __restrict__ v16, __half* __restrict__ v16i)
{
    int gidx = blockIdx.x * 256 + threadIdx.x;   // 262144
    int d8 = gidx & 7;
    int rem = gidx >> 3;
    int kk = rem & 511;
    int bh = rem >> 9;
    int b = bh >> 3, h = bh & 7;

    uint4 x = *(const uint4*)(v16 + ((size_t)(b * T + 2 * kk) * H + h) * DK + d8 * 8);
    uint4 y = *(const uint4*)(v16 + ((size_t)(b * T + 2 * kk + 1) * H + h) * DK + d8 * 8);
    const unsigned short* xs = (const unsigned short*)&x;
    const unsigned short* ys = (const unsigned short*)&y;
    unsigned out[8];
    #pragma unroll
    for (int i = 0; i < 8; i++)
        out[i] = (unsigned)xs[i] | ((unsigned)ys[i] << 16);
    unsigned* dst = (unsigned*)v16i + ((size_t)bh * 512 + kk) * 64 + d8 * 8;
    *(uint4*)(dst + 0) = *(uint4*)(out + 0);
    *(uint4*)(dst + 4) = *(uint4*)(out + 4);
}

// ---------------------------------------------------------------------------
// Fused scores (fp16): cs = scale*(q+u)·k, ps = scale*(q+v)·p -> bf16.
// ---------------------------------------------------------------------------
#define QS 36
__device__ __forceinline__ void score_mma_bf16(
    const unsigned* __restrict__ Q, const unsigned* __restrict__ KP,
    __nv_bfloat16* __restrict__ out, size_t obase, int bi, int bj,
    int wm, int wn, int gid, int tig)
{
    float acc[4][4][4] = {};
    #pragma unroll
    for (int ks = 0; ks < 4; ks++) {
        unsigned af[4][4], bf[4][2];
        #pragma unroll
        for (int mt = 0; mt < 4; mt++) {
            int r = wm * 64 + mt * 16 + gid;
            af[mt][0] = Q[r * QS + ks * 8 + tig];
            af[mt][1] = Q[(r + 8) * QS + ks * 8 + tig];
            af[mt][2] = Q[r * QS + ks * 8 + 4 + tig];
            af[mt][3] = Q[(r + 8) * QS + ks * 8 + 4 + tig];
        }
        #pragma unroll
        for (int nt = 0; nt < 4; nt++) {
            int c = wn * 32 + nt * 8 + gid;
            bf[nt][0] = KP[c * QS + ks * 8 + tig];
            bf[nt][1] = KP[c * QS + ks * 8 + 4 + tig];
        }
        #pragma unroll
        for (int mt = 0; mt < 4; mt++)
            #pragma unroll
            for (int nt = 0; nt < 4; nt++)
                mma_f16(acc[mt][nt], af[mt][0], af[mt][1], af[mt][2], af[mt][3],
                        bf[nt][0], bf[nt][1]);
    }
    const float scale = 0.04419417382415922f;   // 1/sqrt(512)
    #pragma unroll
    for (int mt = 0; mt < 4; mt++) {
        int r0 = bi + wm * 64 + mt * 16 + gid;
        #pragma unroll
        for (int nt = 0; nt < 4; nt++) {
            int c0 = bj + wn * 32 + nt * 8 + 2 * tig;
            __nv_bfloat162 p0 = __floats2bfloat162_rn(acc[mt][nt][0] * scale,
                                                      acc[mt][nt][1] * scale);
            __nv_bfloat162 p1 = __floats2bfloat162_rn(acc[mt][nt][2] * scale,
                                                      acc[mt][nt][3] * scale);
            *(__nv_bfloat162*)&out[obase + (size_t)r0 * T + c0]       = p0;
            *(__nv_bfloat162*)&out[obase + (size_t)(r0 + 8) * T + c0] = p1;
        }
    }
}

__global__ __launch_bounds__(256) void score_fused_f16(
    const __half* __restrict__ q16, const __half* __restrict__ k16,
    const __half* __restrict__ p16, const float* __restrict__ ub,
    const float* __restrict__ vb,
    __nv_bfloat16* __restrict__ cs, __nv_bfloat16* __restrict__ ps)
{
    extern __shared__ unsigned smu[];
    unsigned* Qu = smu;
    unsigned* Qv = smu + 128 * QS;
    unsigned* KP = smu + 2 * 128 * QS;
    __shared__ float sub[DK], svb[DK];

    int bh = blockIdx.z, b = bh >> 3, h = bh & 7;
    int bi = blockIdx.y * 128, bj = blockIdx.x * 128;
    int tid = threadIdx.x, warp = tid >> 5, lane = tid & 31;
    int gid = lane >> 2, tig = lane & 3;
    int wm = warp & 1, wn = warp >> 1;
    size_t obase = (size_t)bh * T * T;

    if (tid < DK) {
        sub[tid] = ub[h * DK + tid];
        svb[tid] = vb[h * DK + tid];
    }

    #pragma unroll
    for (int l = 0; l < 4; l++) {
        int idx = tid + l * 256;
        int row = idx >> 3, c16 = idx & 7;
        cp16g((char*)KP + row * (QS * 4) + c16 * 16,
              k16 + ((size_t)(b * T + bj + row) * H + h) * DK + c16 * 8);
    }
    cp_commit();
    __syncthreads();

    {
        int row = tid >> 1, doff = (tid & 1) * 32;
        const uint4* qp = (const uint4*)(q16 + ((size_t)(b * T + bi + row) * H + h) * DK + doff);
        uint4 r4[4] = { qp[0], qp[1], qp[2], qp[3] };
        const unsigned* rw = (const unsigned*)r4;
        unsigned* qud = &Qu[row * QS + doff / 2];
        unsigned* qvd = &Qv[row * QS + doff / 2];
        #pragma unroll
        for (int u = 0; u < 16; u++) {
            float2 f = unpackh2(rw[u]);
            int d = doff + 2 * u;
            qud[u] = packh2(f.x + sub[d], f.y + sub[d + 1]);
            qvd[u] = packh2(f.x + svb[d], f.y + svb[d + 1]);
        }
    }
    cp_wait0();
    __syncthreads();

    score_mma_bf16(Qu, KP, cs, obase, bi, bj, wm, wn, gid, tig);
    __syncthreads();

    #pragma unroll
    for (int l = 0; l < 4; l++) {
        int idx = tid + l * 256;
        int row = idx >> 3, c16 = idx & 7;
        cp16g((char*)KP + row * (QS * 4) + c16 * 16,
              p16 + ((size_t)(b * T + bj + row) * H + h) * DK + c16 * 8);
    }
    cp_commit();
    cp_wait0();
    __syncthreads();

    score_mma_bf16(Qv, KP, ps, obase, bi, bj, wm, wn, gid, tig);
}

// ---------------------------------------------------------------------------
// Fused rel-shift + softmax: bf16 in, fp16 attn out.
// ---------------------------------------------------------------------------
__device__ __forceinline__ float bf2f(unsigned short u) {
    return __uint_as_float(((unsigned)u) << 16);
}

__global__ __launch_bounds__(256) void softmax_shift_kernel(
    const __nv_bfloat16* __restrict__ cs, const __nv_bfloat16* __restrict__ ps,
    __half* __restrict__ attn)
{
    int i  = blockIdx.x;
    int bh = blockIdx.y;
    int tid = threadIdx.x;
    size_t base = (size_t)bh * T * T;
    int j0 = tid * 4;

    ushort4 craw = *(const ushort4*)&cs[base + (size_t)i * T + j0];
    const unsigned short* cw = (const unsigned short*)&craw;

    float vals[4];
    float mx = -3.4e38f;
    #pragma unroll
    for (int l = 0; l < 4; l++) {
        int j = j0 + l;
        float pv;
        if (j <= i)
            pv = bf2f(*(const unsigned short*)&ps[base + (size_t)i * T + (T + j - i - 1)]);
        else if (j == i + 1)
            pv = 0.0f;
        else
            pv = bf2f(*(const unsigned short*)&ps[base + (size_t)(i + 1) * T + (j - i - 2)]);
        float s = bf2f(cw[l]) + pv;
        vals[l] = s;
        mx = fmaxf(mx, s);
    }

    __shared__ float red[8];
    #pragma unroll
    for (int o = 16; o > 0; o >>= 1) mx = fmaxf(mx, __shfl_xor_sync(0xffffffffu, mx, o));
    if ((tid & 31) == 0) red[tid >> 5] = mx;
    __syncthreads();
    if (tid == 0) {
        float m = red[0];
        #pragma unroll
        for (int w = 1; w < 8; w++) m = fmaxf(m, red[w]);
        red[0] = m;
    }
    __syncthreads();
    mx = red[0];
    __syncthreads();

    float sum = 0.f;
    #pragma unroll
    for (int l = 0; l < 4; l++) { vals[l] = __expf(vals[l] - mx); sum += vals[l]; }
    #pragma unroll
    for (int o = 16; o > 0; o >>= 1) sum += __shfl_xor_sync(0xffffffffu, sum, o);
    if ((tid & 31) == 0) red[tid >> 5] = sum;
    __syncthreads();
    if (tid == 0) {
        float s = 0.f;
        #pragma unroll
        for (int w = 0; w < 8; w++) s += red[w];
        red[0] = s;
    }
    __syncthreads();
    float rinv = 1.0f / red[0];
    uint2 outp;
    outp.x = packh2(vals[0] * rinv, vals[1] * rinv);
    outp.y = packh2(vals[2] * rinv, vals[3] * rinv);
    *(uint2*)&attn[base + (size_t)i * T + j0] = outp;
}

// ---------------------------------------------------------------------------
// Context (fp16): ctx16 = attn @ v. Block 128x64, 8 warps 4x2, K-step 32, 3-stage.
// ---------------------------------------------------------------------------
__global__ __launch_bounds__(256, 2) void context_f16(
    const __half* __restrict__ attn, const __half* __restrict__ v16i,
    __half* __restrict__ ctx16)
{
    __shared__ unsigned As[3][128 * 20];
    __shared__ unsigned Vs[3][16 * 72];
    int bh = blockIdx.y, b = bh >> 3, h = bh & 7;
    int bm = blockIdx.x * 128;
    int tid = threadIdx.x, warp = tid >> 5, lane = tid & 31;
    int gid = lane >> 2, tig = lane & 3;
    int wm = warp >> 1, wn = warp & 1;
    size_t abase = (size_t)bh * T * T;
    const unsigned* vsrc = (const unsigned*)v16i + (size_t)bh * 512 * 64;

    const int nsteps = T / 32;   // 32

    #pragma unroll
    for (int s = 0; s < 2; s++) {
        int k0 = s * 32;
        #pragma unroll
        for (int l = 0; l < 2; l++) {
            int idx = tid + l * 256;
            int row = idx >> 2, c = idx & 3;
            cp16g((char*)As[s] + row * 80 + c * 16,
                  attn + abase + (size_t)(bm + row) * T + k0 + c * 8);
        }
        {
            int kk = tid >> 4, c = tid & 15;
            cp16g((char*)Vs[s] + kk * 288 + c * 16,
                  vsrc + (size_t)(k0 / 2 + kk) * 64 + c * 4);
        }
        cp_commit();
    }

    float acc[2][4][4] = {};
    for (int s = 0; s < nsteps; s++) {
        cp_wait1();
        __syncthreads();
        int st = s % 3;
        if (s + 2 < nsteps) {
            int k0 = (s + 2) * 32, st2 = (s + 2) % 3;
            #pragma unroll
            for (int l = 0; l < 2; l++) {
                int idx = tid + l * 256;
                int row = idx >> 2, c = idx & 3;
                cp16g((char*)As[st2] + row * 80 + c * 16,
                      attn + abase + (size_t)(bm + row) * T + k0 + c * 8);
            }
            int kk = tid >> 4, c = tid & 15;
            cp16g((char*)Vs[st2] + kk * 288 + c * 16,
                  vsrc + (size_t)(k0 / 2 + kk) * 64 + c * 4);
        }
        cp_commit();

        #pragma unroll
        for (int ks = 0; ks < 2; ks++) {
            unsigned af[2][4], bf[4][2];
            #pragma unroll
            for (int mt = 0; mt < 2; mt++) {
                int r = wm * 32 + mt * 16 + gid;
                af[mt][0] = As[st][r * 20 + ks * 8 + tig];
                af[mt][1] = As[st][(r + 8) * 20 + ks * 8 + tig];
                af[mt][2] = As[st][r * 20 + ks * 8 + 4 + tig];
                af[mt][3] = As[st][(r + 8) * 20 + ks * 8 + 4 + tig];
            }
            #pragma unroll
            for (int nt = 0; nt < 4; nt++) {
                int c = wn * 32 + nt * 8 + gid;
                bf[nt][0] = Vs[st][(ks * 8 + tig) * 72 + c];
                bf[nt][1] = Vs[st][(ks * 8 + 4 + tig) * 72 + c];
            }
            #pragma unroll
            for (int mt = 0; mt < 2; mt++)
                #pragma unroll
                for (int nt = 0; nt < 4; nt++)
                    mma_f16(acc[mt][nt], af[mt][0], af[mt][1], af[mt][2], af[mt][3],
                            bf[nt][0], bf[nt][1]);
        }
    }

    #pragma unroll
    for (int mt = 0; mt < 2; mt++) {
        int r0 = bm + wm * 32 + mt * 16 + gid;
        #pragma unroll
        for (int nt = 0; nt < 4; nt++) {
            int c0 = wn * 32 + nt * 8 + 2 * tig;
            *(unsigned*)&ctx16[((size_t)(b * T + r0) * H + h) * DK + c0] =
                packh2(acc[mt][nt][0], acc[mt][nt][1]);
            *(unsigned*)&ctx16[((size_t)(b * T + r0 + 8) * H + h) * DK + c0] =
                packh2(acc[mt][nt][2], acc[mt][nt][3]);
        }
    }
}

// ---------------------------------------------------------------------------
extern "C" void kernel_launch(void* const* d_in, const int* in_sizes, int n_in,
                              void* d_out, int out_size)
{
    const float* query = (const float*)d_in[0];
    const float* key   = (const float*)d_in[1];
    const float* value = (const float*)d_in[2];
    const float* pos   = (const float*)d_in[3];
    const float* Wq = (const float*)d_in[4];
    const float* bq = (const float*)d_in[5];
    const float* Wk = (const float*)d_in[6];
    const float* bk = (const float*)d_in[7];
    const float* Wv = (const float*)d_in[8];
    const float* bv = (const float*)d_in[9];
    const float* Wp = (const float*)d_in[10];
    const float* ub = (const float*)d_in[11];
    const float* vb = (const float*)d_in[12];
    const float* Wo = (const float*)d_in[13];
    const float* bo = (const float*)d_in[14];
    float* out = (float*)d_out;

    __half *x16, *q16, *k16, *v16, *p16, *v16i, *attn16, *ctx16;
    unsigned* w16;
    __nv_bfloat16 *cs, *ps;
    cudaGetSymbolAddress((void**)&x16,    g_x16);
    cudaGetSymbolAddress((void**)&w16,    g_w16);
    cudaGetSymbolAddress((void**)&q16,    g_q16);
    cudaGetSymbolAddress((void**)&k16,    g_k16);
    cudaGetSymbolAddress((void**)&v16,    g_v16);
    cudaGetSymbolAddress((void**)&p16,    g_p16);
    cudaGetSymbolAddress((void**)&v16i,   g_v16i);
    cudaGetSymbolAddress((void**)&cs,     g_cs);
    cudaGetSymbolAddress((void**)&ps,     g_ps);
    cudaGetSymbolAddress((void**)&attn16, g_attn16);
    cudaGetSymbolAddress((void**)&ctx16,  g_ctx16);

    const int SMEM_GEMM  = (3 * 128 * 20 + 3 * 16 * 136) * 4;   // 56832 B
    const int SMEM_SCORE = 3 * 128 * QS * 4;                    // 55296 B
    cudaFuncSetAttribute(gemm_h16,
        cudaFuncAttributeMaxDynamicSharedMemorySize, SMEM_GEMM);
    cudaFuncSetAttribute(score_fused_f16,
        cudaFuncAttributeMaxDynamicSharedMemorySize, SMEM_SCORE);

    // one-time conversions
    ActPtrs ap;
    ap.in[0] = query; ap.in[1] = key; ap.in[2] = value; ap.in[3] = pos;
    ap.out[0] = x16 + 0 * (size_t)BT * D;
    ap.out[1] = x16 + 1 * (size_t)BT * D;
    ap.out[2] = x16 + 2 * (size_t)BT * D;
    ap.out[3] = x16 + 3 * (size_t)BT * D;
    cvt_act<<<dim3(BT * D / (8 * 256), 4), 256>>>(ap);

    WPtrs wp;
    wp.in[0] = Wq; wp.in[1] = Wk; wp.in[2] = Wv; wp.in[3] = Wp; wp.in[4] = Wo;
    for (int i = 0; i < 5; i++) wp.out[i] = w16 + (size_t)i * (D * D / 2);
    cvt_w<<<dim3(128, 5), 256>>>(wp);

    // GEMMs
    GArgs ga;
    ga.A[0] = ap.out[0]; ga.A[1] = ap.out[1]; ga.A[2] = ap.out[2]; ga.A[3] = ap.out[3];
    ga.A[4] = ctx16;
    for (int i = 0; i < 5; i++) ga.W[i] = wp.out[i];
    ga.bias[0] = bq; ga.bias[1] = bk; ga.bias[2] = bv; ga.bias[3] = nullptr; ga.bias[4] = bo;
    ga.Ch[0] = q16; ga.Ch[1] = k16; ga.Ch[2] = v16; ga.Ch[3] = p16; ga.Ch[4] = nullptr;
    ga.Cf[0] = ga.Cf[1] = ga.Cf[2] = ga.Cf[3] = nullptr; ga.Cf[4] = out;

    dim3 gproj(D / 128, BT / 128, 4);       // (4, 64, 4)
    gemm_h16<<<gproj, 256, SMEM_GEMM>>>(ga, 0);

    v_reshape<<<1024, 256>>>(v16, v16i);

    dim3 gsc(T / 128, T / 128, B * H);      // (8, 8, 64)
    score_fused_f16<<<gsc, 256, SMEM_SCORE>>>(q16, k16, p16, ub, vb, cs, ps);

    dim3 gsm(T, B * H);                     // (1024, 64)
    softmax_shift_kernel<<<gsm, 256>>>(cs, ps, attn16);

    dim3 gctx(T / 128, B * H);              // (8, 64)
    context_f16<<<gctx, 256>>>(attn16, v16i, ctx16);

    dim3 gout(D / 128, BT / 128, 1);        // (4, 64)
    gemm_h16<<<gout, 256, SMEM_GEMM>>>(ga, 4);
}